// round 13
// baseline (speedup 1.0000x reference)
#include <cuda_runtime.h>
#include <cuda_bf16.h>
#include <cstdint>

// ---------------- problem constants ----------------
#define NN    50000
#define INF   768
#define HH    128
#define RR    3

typedef __nv_bfloat16 bf16;

// ---------------- scratch (device globals; no runtime alloc) ----------------
__device__ bf16  g_B1h[512 * INF];
__device__ bf16  g_B1l[512 * INF];
__device__ bf16  g_B2h[512 * HH];
__device__ bf16  g_B2l[512 * HH];
__device__ bf16  g_B3h[512 * HH];
__device__ bf16  g_B3l[512 * HH];
__device__ bf16  g_Weh[256 * 128];
__device__ bf16  g_Wel[256 * 128];
__device__ bf16  g_xh[(size_t)NN * INF];      // activation hi (bf16)
__device__ bf16  g_xl[(size_t)NN * INF];      // activation lo
__device__ float g_hcomb[(size_t)NN * 512];   // GEMM out [N,512]; reused as UV [N,256]
__device__ int   g_offs[NN + 1];
__device__ int   g_cur[NN];
__device__ int   g_cnt3[NN * RR];
__device__ int   g_epack[800000 + 64];        // CSR edge data: src | et<<28

// ================= helpers =================
__device__ __forceinline__ uint32_t smem_u32(const void* p) {
    uint32_t a;
    asm("{ .reg .u64 t; cvta.to.shared.u64 t, %1; cvt.u32.u64 %0, t; }" : "=r"(a) : "l"(p));
    return a;
}
// L2-only policy: staged tiles are consumed exactly once from smem.
__device__ __forceinline__ void cpasync16(uint32_t saddr, const void* g) {
    asm volatile("cp.async.cg.shared.global [%0], [%1], 16;" :: "r"(saddr), "l"(g));
}
#define CP_COMMIT() asm volatile("cp.async.commit_group;" ::: "memory")
#define CP_WAIT1()  asm volatile("cp.async.wait_group 1;" ::: "memory")
#define CP_WAIT0()  asm volatile("cp.async.wait_group 0;" ::: "memory")

__device__ __forceinline__ void ldsm4(uint32_t (&r)[4], uint32_t addr) {
    asm volatile("ldmatrix.sync.aligned.m8n8.x4.shared.b16 {%0,%1,%2,%3}, [%4];"
                 : "=r"(r[0]), "=r"(r[1]), "=r"(r[2]), "=r"(r[3]) : "r"(addr));
}
__device__ __forceinline__ void mma_bf16(float (&d)[4], const uint32_t (&a)[4],
                                         uint32_t b0, uint32_t b1) {
    asm volatile("mma.sync.aligned.m16n8k16.row.col.f32.bf16.bf16.f32 "
                 "{%0,%1,%2,%3}, {%4,%5,%6,%7}, {%8,%9}, {%0,%1,%2,%3};"
                 : "+f"(d[0]), "+f"(d[1]), "+f"(d[2]), "+f"(d[3])
                 : "r"(a[0]), "r"(a[1]), "r"(a[2]), "r"(a[3]), "r"(b0), "r"(b1));
}

// smem tile: 128 rows x 4 chunks of 16B. XOR swizzle.
__device__ __forceinline__ uint32_t swz(int row, int chunk) {
    return (uint32_t)(((row << 2) + (chunk ^ ((row >> 1) & 3))) << 4);
}
#define TILE_B  8192
#define STAGE_B (4 * TILE_B)
#define NSTAGE  3
#define DYN_SMEM (NSTAGE * STAGE_B)    // 96 KB

// ---------------- stage loader ----------------
__device__ __forceinline__ void load_stage_dense(
    uint32_t sb, const bf16* __restrict__ Ah, const bf16* __restrict__ Al,
    const bf16* __restrict__ Bh, const bf16* __restrict__ Bl,
    int K, int bm, int n0, int k0, int M, int tid) {
#pragma unroll
    for (int i = 0; i < 2; i++) {
        int cid = tid * 2 + i;
        int row = cid >> 2, ch = cid & 3;
        int gm = bm + row; if (gm >= M) gm = M - 1;
        size_t ga = (size_t)gm * K + k0 + ch * 8;
        uint32_t so = swz(row, ch);
        cpasync16(sb + so, Ah + ga);
        cpasync16(sb + TILE_B + so, Al + ga);
        size_t gb = (size_t)(n0 + row) * K + k0 + ch * 8;
        cpasync16(sb + 2 * TILE_B + so, Bh + gb);
        cpasync16(sb + 3 * TILE_B + so, Bl + gb);
    }
}

// ---------------- warp-tile compute (64x32, bf16x3) ----------------
__device__ __forceinline__ void compute_stage(float (&acc)[4][4][4], uint32_t sb,
                                              int m0w, int n0w, int lane) {
#pragma unroll
    for (int kf = 0; kf < 2; kf++) {
        uint32_t ah[4][4], al[4][4], bh[2][4], bl[2][4];
        const int arow = lane & 15;
        const int ach = kf * 2 + (lane >> 4);
        const int brow = n0w + ((lane >> 4) << 3) + (lane & 7);
        const int bch = kf * 2 + ((lane >> 3) & 1);
#pragma unroll
        for (int mf = 0; mf < 4; mf++)
            ldsm4(ah[mf], sb + swz(m0w + mf * 16 + arow, ach));
#pragma unroll
        for (int p = 0; p < 2; p++)
            ldsm4(bh[p], sb + 2 * TILE_B + swz(brow + p * 16, bch));
#pragma unroll
        for (int mf = 0; mf < 4; mf++)
#pragma unroll
            for (int nf = 0; nf < 4; nf++)
                mma_bf16(acc[mf][nf], ah[mf], bh[nf >> 1][(nf & 1) * 2], bh[nf >> 1][(nf & 1) * 2 + 1]);
#pragma unroll
        for (int p = 0; p < 2; p++)
            ldsm4(bl[p], sb + 3 * TILE_B + swz(brow + p * 16, bch));
#pragma unroll
        for (int mf = 0; mf < 4; mf++)
#pragma unroll
            for (int nf = 0; nf < 4; nf++)
                mma_bf16(acc[mf][nf], ah[mf], bl[nf >> 1][(nf & 1) * 2], bl[nf >> 1][(nf & 1) * 2 + 1]);
#pragma unroll
        for (int mf = 0; mf < 4; mf++)
            ldsm4(al[mf], sb + TILE_B + swz(m0w + mf * 16 + arow, ach));
#pragma unroll
        for (int mf = 0; mf < 4; mf++)
#pragma unroll
            for (int nf = 0; nf < 4; nf++)
                mma_bf16(acc[mf][nf], al[mf], bh[nf >> 1][(nf & 1) * 2], bh[nf >> 1][(nf & 1) * 2 + 1]);
    }
}

// ---------------- GEMM: 3-stage cp.async pipeline ----------------
__global__ __launch_bounds__(256)
void gemm_mma(const bf16* __restrict__ Ah, const bf16* __restrict__ Al,
              const bf16* __restrict__ Bh, const bf16* __restrict__ Bl,
              float* __restrict__ C, int M, int K, int ldc) {
    extern __shared__ char dsm[];
    const uint32_t sb = smem_u32(dsm);
    const int tid = threadIdx.x, lane = tid & 31, wid = tid >> 5;
    const int bm = blockIdx.y * 128, n0 = blockIdx.x * 128;
    const int m0w = (wid >> 2) * 64, n0w = (wid & 3) * 32;
    float acc[4][4][4];
#pragma unroll
    for (int a = 0; a < 4; a++)
#pragma unroll
        for (int b = 0; b < 4; b++)
#pragma unroll
            for (int c = 0; c < 4; c++) acc[a][b][c] = 0.f;

    const int niter = K / 32;   // always >= 2 here
    load_stage_dense(sb, Ah, Al, Bh, Bl, K, bm, n0, 0, M, tid);
    CP_COMMIT();
    load_stage_dense(sb + STAGE_B, Ah, Al, Bh, Bl, K, bm, n0, 32, M, tid);
    CP_COMMIT();

    int buf = 0;
    for (int it = 0; it < niter; it++) {
        if (it + 1 < niter) CP_WAIT1(); else CP_WAIT0();
        __syncthreads();
        if (it + 2 < niter) {
            int nb = buf + 2; if (nb >= NSTAGE) nb -= NSTAGE;
            load_stage_dense(sb + nb * STAGE_B, Ah, Al, Bh, Bl, K, bm, n0, (it + 2) * 32, M, tid);
            CP_COMMIT();
        }
        compute_stage(acc, sb + buf * STAGE_B, m0w, n0w, lane);
        if (++buf == NSTAGE) buf = 0;
    }

#pragma unroll
    for (int mf = 0; mf < 4; mf++) {
#pragma unroll
        for (int nf = 0; nf < 4; nf++) {
            int col = n0 + n0w + nf * 8 + (lane & 3) * 2;
            int r0 = bm + m0w + mf * 16 + (lane >> 2);
            if (r0 < M)
                *(float2*)&C[(size_t)r0 * ldc + col] = make_float2(acc[mf][nf][0], acc[mf][nf][1]);
            int r1 = r0 + 8;
            if (r1 < M)
                *(float2*)&C[(size_t)r1 * ldc + col] = make_float2(acc[mf][nf][2], acc[mf][nf][3]);
        }
    }
}

// ---------------- prep: pack_all + cnt + split fused via block-range dispatch ----------------
__device__ __forceinline__ void pack_one(float v, bf16* __restrict__ Bh,
                                         bf16* __restrict__ Bl, int idx) {
    bf16 h = __float2bfloat16(v);
    Bh[idx] = h;
    Bl[idx] = __float2bfloat16(v - __bfloat162float(h));
}
__device__ __forceinline__ float layer_w(const float* __restrict__ W_root,
                                         const float* __restrict__ W_rel,
                                         int idx, int K) {
    int n = idx / K, k = idx % K;
    if (n < HH) return W_root[k * HH + n];
    return W_rel[((size_t)((n >> 7) - 1) * K + k) * HH + (n & 127)];
}
#define P1 (512 * INF)
#define P2 (512 * HH)
#define PACK_TOTAL  (P1 + 2 * P2 + 256 * 128)
#define PACK_BLOCKS ((PACK_TOTAL + 255) / 256)
#define SPLIT_N4    (NN * INF / 4)
#define SPLIT_BLOCKS ((SPLIT_N4 + 255) / 256)

__global__ __launch_bounds__(256)
void prep_kernel(const float* __restrict__ Wr1, const float* __restrict__ Wrel1,
                 const float* __restrict__ Wr2, const float* __restrict__ Wrel2,
                 const float* __restrict__ Wr3, const float* __restrict__ Wrel3,
                 const float* __restrict__ We1,
                 bf16* B1h, bf16* B1l, bf16* B2h, bf16* B2l,
                 bf16* B3h, bf16* B3l, bf16* Weh, bf16* Wel,
                 const int* __restrict__ dst, const int* __restrict__ et,
                 int* __restrict__ cnt3, int E, int cntBlocks,
                 const float* __restrict__ x, bf16* __restrict__ xh, bf16* __restrict__ xl) {
    int blk = blockIdx.x;
    if (blk < PACK_BLOCKS) {
        int idx = blk * 256 + threadIdx.x;
        if (idx < P1) {
            pack_one(layer_w(Wr1, Wrel1, idx, INF), B1h, B1l, idx);
        } else if (idx < P1 + P2) {
            int i = idx - P1;
            pack_one(layer_w(Wr2, Wrel2, i, HH), B2h, B2l, i);
        } else if (idx < P1 + 2 * P2) {
            int i = idx - P1 - P2;
            pack_one(layer_w(Wr3, Wrel3, i, HH), B3h, B3l, i);
        } else if (idx < PACK_TOTAL) {
            int i = idx - P1 - 2 * P2;
            int n = i / 128, k = i % 128;
            float v = (n < 128) ? We1[k * 128 + n] : We1[(128 + k) * 128 + (n - 128)];
            pack_one(v, Weh, Wel, i);
        }
        return;
    }
    blk -= PACK_BLOCKS;
    if (blk < cntBlocks) {
        int i = blk * 256 + threadIdx.x;
        if (i < E) atomicAdd(&cnt3[dst[i] * RR + et[i]], 1);
        return;
    }
    blk -= cntBlocks;
    {
        int i = blk * 256 + threadIdx.x;
        if (i >= SPLIT_N4) return;
        float4 v = ((const float4*)x)[i];
        bf16 h0 = __float2bfloat16(v.x), h1 = __float2bfloat16(v.y);
        bf16 h2 = __float2bfloat16(v.z), h3 = __float2bfloat16(v.w);
        ((__nv_bfloat162*)xh)[i * 2]     = __nv_bfloat162(h0, h1);
        ((__nv_bfloat162*)xh)[i * 2 + 1] = __nv_bfloat162(h2, h3);
        ((__nv_bfloat162*)xl)[i * 2]     = __nv_bfloat162(__float2bfloat16(v.x - __bfloat162float(h0)),
                                                          __float2bfloat16(v.y - __bfloat162float(h1)));
        ((__nv_bfloat162*)xl)[i * 2 + 1] = __nv_bfloat162(__float2bfloat16(v.z - __bfloat162float(h2)),
                                                          __float2bfloat16(v.w - __bfloat162float(h3)));
    }
}

// ---------------- scan over cnt3 triplets -> offs ----------------
__global__ void scan_kernel(const int* __restrict__ cnt3, int* __restrict__ offs) {
    __shared__ int warp_sums[32];
    __shared__ int s_carry;
    const int t = threadIdx.x;          // 1024 threads, single block
    const int lane = t & 31, w = t >> 5;
    if (t == 0) { s_carry = 0; offs[0] = 0; }
    __syncthreads();
    for (int base = 0; base < NN; base += 1024) {
        int i = base + t;
        int v = 0;
        if (i < NN)
            v = cnt3[i * RR + 0] + cnt3[i * RR + 1] + cnt3[i * RR + 2];
        int x = v;
#pragma unroll
        for (int o = 1; o < 32; o <<= 1) {
            int y = __shfl_up_sync(0xFFFFFFFFu, x, o);
            if (lane >= o) x += y;
        }
        if (lane == 31) warp_sums[w] = x;
        __syncthreads();
        if (w == 0) {
            int s = warp_sums[lane];
#pragma unroll
            for (int o = 1; o < 32; o <<= 1) {
                int y = __shfl_up_sync(0xFFFFFFFFu, s, o);
                if (lane >= o) s += y;
            }
            warp_sums[lane] = s;
        }
        __syncthreads();
        int incl = x + (w > 0 ? warp_sums[w - 1] : 0) + s_carry;
        if (i < NN) offs[i + 1] = incl;
        __syncthreads();
        if (t == 1023) s_carry = incl;
        __syncthreads();
    }
}

__global__ void fill_kernel(const int* __restrict__ src, const int* __restrict__ dst,
                            const int* __restrict__ et, const int* __restrict__ offs,
                            int* __restrict__ cur, int* __restrict__ epack, int E) {
    int i = blockIdx.x * blockDim.x + threadIdx.x;
    if (i >= E) return;
    int d = dst[i];
    int p = atomicAdd(&cur[d], 1);
    epack[offs[d] + p] = src[i] | (et[i] << 28);
}

// ---------------- fused aggregation: warp/node, branch-free weighted sum ----------------
__global__ __launch_bounds__(256)
void agg_combine(const float* __restrict__ hcomb, const int* __restrict__ offs,
                 const int* __restrict__ epack, const int* __restrict__ cnt3,
                 const float* __restrict__ b,
                 bf16* __restrict__ xh, bf16* __restrict__ xl, int do_relu) {
    int node = (blockIdx.x * blockDim.x + threadIdx.x) >> 5;
    int lane = threadIdx.x & 31;
    if (node >= NN) return;
    const int o0 = offs[node], o1 = offs[node + 1];
    const float w0 = 1.f / (float)max(__ldg(&cnt3[node * RR + 0]), 1);
    const float w1 = 1.f / (float)max(__ldg(&cnt3[node * RR + 1]), 1);
    const float w2 = 1.f / (float)max(__ldg(&cnt3[node * RR + 2]), 1);

    float4 root = *(const float4*)&hcomb[(size_t)node * 512 + lane * 4];
    float4 bb = *(const float4*)&b[lane * 4];
    float tx = root.x + bb.x, ty = root.y + bb.y;
    float tz = root.z + bb.z, tw = root.w + bb.w;

    const float* __restrict__ hb = hcomb + 128 + lane * 4;
    int e = o0;
    for (; e + 4 <= o1; e += 4) {
        int p0 = __ldg(&epack[e + 0]);
        int p1 = __ldg(&epack[e + 1]);
        int p2 = __ldg(&epack[e + 2]);
        int p3 = __ldg(&epack[e + 3]);
        int r0 = (unsigned)p0 >> 28, r1 = (unsigned)p1 >> 28;
        int r2 = (unsigned)p2 >> 28, r3 = (unsigned)p3 >> 28;
        float4 v0 = __ldg((const float4*)(hb + ((size_t)(p0 & 0x0FFFFFFF) * 512 + (r0 << 7))));
        float4 v1 = __ldg((const float4*)(hb + ((size_t)(p1 & 0x0FFFFFFF) * 512 + (r1 << 7))));
        float4 v2 = __ldg((const float4*)(hb + ((size_t)(p2 & 0x0FFFFFFF) * 512 + (r2 << 7))));
        float4 v3 = __ldg((const float4*)(hb + ((size_t)(p3 & 0x0FFFFFFF) * 512 + (r3 << 7))));
        float ws0 = (r0 == 0) ? w0 : ((r0 == 1) ? w1 : w2);
        float ws1 = (r1 == 0) ? w0 : ((r1 == 1) ? w1 : w2);
        float ws2 = (r2 == 0) ? w0 : ((r2 == 1) ? w1 : w2);
        float ws3 = (r3 == 0) ? w0 : ((r3 == 1) ? w1 : w2);
        tx += v0.x * ws0 + v1.x * ws1 + v2.x * ws2 + v3.x * ws3;
        ty += v0.y * ws0 + v1.y * ws1 + v2.y * ws2 + v3.y * ws3;
        tz += v0.z * ws0 + v1.z * ws1 + v2.z * ws2 + v3.z * ws3;
        tw += v0.w * ws0 + v1.w * ws1 + v2.w * ws2 + v3.w * ws3;
    }
    if (e + 2 <= o1) {
        int p0 = __ldg(&epack[e + 0]);
        int p1 = __ldg(&epack[e + 1]);
        int r0 = (unsigned)p0 >> 28, r1 = (unsigned)p1 >> 28;
        float4 v0 = __ldg((const float4*)(hb + ((size_t)(p0 & 0x0FFFFFFF) * 512 + (r0 << 7))));
        float4 v1 = __ldg((const float4*)(hb + ((size_t)(p1 & 0x0FFFFFFF) * 512 + (r1 << 7))));
        float ws0 = (r0 == 0) ? w0 : ((r0 == 1) ? w1 : w2);
        float ws1 = (r1 == 0) ? w0 : ((r1 == 1) ? w1 : w2);
        tx += v0.x * ws0 + v1.x * ws1;
        ty += v0.y * ws0 + v1.y * ws1;
        tz += v0.z * ws0 + v1.z * ws1;
        tw += v0.w * ws0 + v1.w * ws1;
        e += 2;
    }
    if (e < o1) {
        int p0 = __ldg(&epack[e]);
        int r0 = (unsigned)p0 >> 28;
        float4 v0 = __ldg((const float4*)(hb + ((size_t)(p0 & 0x0FFFFFFF) * 512 + (r0 << 7))));
        float ws0 = (r0 == 0) ? w0 : ((r0 == 1) ? w1 : w2);
        tx += v0.x * ws0; ty += v0.y * ws0; tz += v0.z * ws0; tw += v0.w * ws0;
    }

    if (do_relu) {
        tx = fmaxf(tx, 0.f); ty = fmaxf(ty, 0.f);
        tz = fmaxf(tz, 0.f); tw = fmaxf(tw, 0.f);
    }
    size_t idx = (size_t)node * HH + lane * 4;
    bf16 h0 = __float2bfloat16(tx), h1 = __float2bfloat16(ty);
    bf16 h2 = __float2bfloat16(tz), h3 = __float2bfloat16(tw);
    __nv_bfloat162 hh0(h0, h1), hh1(h2, h3);
    *(uint2*)&xh[idx] = make_uint2(*(uint32_t*)&hh0, *(uint32_t*)&hh1);
    __nv_bfloat162 ll0(__float2bfloat16(tx - __bfloat162float(h0)),
                       __float2bfloat16(ty - __bfloat162float(h1)));
    __nv_bfloat162 ll1(__float2bfloat16(tz - __bfloat162float(h2)),
                       __float2bfloat16(tw - __bfloat162float(h3)));
    *(uint2*)&xl[idx] = make_uint2(*(uint32_t*)&ll0, *(uint32_t*)&ll1);
}

// ---------------- tail: edge_apply + node_head fused via block-range dispatch ----------------
__global__ __launch_bounds__(256)
void tail_kernel(const float* __restrict__ UV,
                 const int* __restrict__ src, const int* __restrict__ dst,
                 const float* __restrict__ be1, const float* __restrict__ We2,
                 const float* __restrict__ be2, float* __restrict__ edge_out, int E,
                 int edgeBlocks,
                 const bf16* __restrict__ xh, const bf16* __restrict__ xl,
                 const float* __restrict__ Wn1, const float* __restrict__ bn1,
                 const float* __restrict__ Wn2, const float* __restrict__ bn2,
                 float* __restrict__ node_out) {
    __shared__ union {
        struct { float be1s[128]; float w2s[384]; } edge;
        struct {
            float W1[128 * 64];
            float b1[64];
            float W2[128];
            float x[4][128];
            float part[8][2];
        } node;
    } sm;

    const int tid = threadIdx.x, lane = tid & 31;
    if (blockIdx.x < (unsigned)edgeBlocks) {
        // ---- edge path ----
        if (tid < 128) sm.edge.be1s[tid] = be1[tid];
        for (int v = tid; v < 384; v += 256) sm.edge.w2s[v] = We2[v];
        __syncthreads();
        int gw = (blockIdx.x * 256 + tid) >> 5;
        if (gw >= E) return;
        int s = src[gw], d = dst[gw];
        float4 u = __ldg((const float4*)(UV + (size_t)s * 256 + lane * 4));
        float4 v = __ldg((const float4*)(UV + (size_t)d * 256 + 128 + lane * 4));
        int c = lane * 4;
        float a0 = 0.f, a1 = 0.f, a2 = 0.f;
        float h;
        h = fmaxf(u.x + v.x + sm.edge.be1s[c + 0], 0.f); a0 += h * sm.edge.w2s[(c + 0) * 3]; a1 += h * sm.edge.w2s[(c + 0) * 3 + 1]; a2 += h * sm.edge.w2s[(c + 0) * 3 + 2];
        h = fmaxf(u.y + v.y + sm.edge.be1s[c + 1], 0.f); a0 += h * sm.edge.w2s[(c + 1) * 3]; a1 += h * sm.edge.w2s[(c + 1) * 3 + 1]; a2 += h * sm.edge.w2s[(c + 1) * 3 + 2];
        h = fmaxf(u.z + v.z + sm.edge.be1s[c + 2], 0.f); a0 += h * sm.edge.w2s[(c + 2) * 3]; a1 += h * sm.edge.w2s[(c + 2) * 3 + 1]; a2 += h * sm.edge.w2s[(c + 2) * 3 + 2];
        h = fmaxf(u.w + v.w + sm.edge.be1s[c + 3], 0.f); a0 += h * sm.edge.w2s[(c + 3) * 3]; a1 += h * sm.edge.w2s[(c + 3) * 3 + 1]; a2 += h * sm.edge.w2s[(c + 3) * 3 + 2];
#pragma unroll
        for (int o = 16; o; o >>= 1) {
            a0 += __shfl_xor_sync(0xFFFFFFFFu, a0, o);
            a1 += __shfl_xor_sync(0xFFFFFFFFu, a1, o);
            a2 += __shfl_xor_sync(0xFFFFFFFFu, a2, o);
        }
        if (lane == 0) {
            edge_out[(size_t)gw * 3 + 0] = a0 + __ldg(&be2[0]);
            edge_out[(size_t)gw * 3 + 1] = a1 + __ldg(&be2[1]);
            edge_out[(size_t)gw * 3 + 2] = a2 + __ldg(&be2[2]);
        }
        return;
    }
    // ---- node path: 64 nodes per block ----
    const int team = tid >> 6, t = tid & 63;
    const int wid = tid >> 5;
    for (int i = tid; i < 128 * 64; i += 256) sm.node.W1[i] = Wn1[i];
    if (tid < 64) sm.node.b1[tid] = bn1[tid];
    if (tid < 128) sm.node.W2[tid] = Wn2[tid];
    float b20 = __ldg(&bn2[0]), b21 = __ldg(&bn2[1]);
    __syncthreads();
    const int base = (blockIdx.x - edgeBlocks) * 64;
#pragma unroll 1
    for (int it = 0; it < 16; it++) {
        int node = base + it * 4 + team;
        bool ok = node < NN;
        if (ok) {
            size_t off = (size_t)node * HH;
            sm.node.x[team][t]      = __bfloat162float(xh[off + t])      + __bfloat162float(xl[off + t]);
            sm.node.x[team][t + 64] = __bfloat162float(xh[off + t + 64]) + __bfloat162float(xl[off + t + 64]);
        }
        __syncthreads();
        float p0 = 0.f, p1 = 0.f;
        if (ok) {
            float acc = sm.node.b1[t];
#pragma unroll
            for (int k = 0; k < 128; k++) acc += sm.node.x[team][k] * sm.node.W1[k * 64 + t];
            float hgt = fmaxf(acc, 0.f);
            p0 = hgt * sm.node.W2[t * 2 + 0];
            p1 = hgt * sm.node.W2[t * 2 + 1];
        }
#pragma unroll
        for (int o = 16; o; o >>= 1) {
            p0 += __shfl_xor_sync(0xFFFFFFFFu, p0, o);
            p1 += __shfl_xor_sync(0xFFFFFFFFu, p1, o);
        }
        if (lane == 0) { sm.node.part[wid][0] = p0; sm.node.part[wid][1] = p1; }
        __syncthreads();
        if (ok && t == 0) {
            node_out[(size_t)node * 2 + 0] = sm.node.part[team * 2][0] + sm.node.part[team * 2 + 1][0] + b20;
            node_out[(size_t)node * 2 + 1] = sm.node.part[team * 2][1] + sm.node.part[team * 2 + 1][1] + b21;
        }
        __syncthreads();
    }
}

// ---------------- launch ----------------
extern "C" void kernel_launch(void* const* d_in, const int* in_sizes, int n_in,
                              void* d_out, int out_size) {
    const float* x       = (const float*)d_in[0];
    const int*   ei      = (const int*)d_in[1];
    const int*   et      = (const int*)d_in[2];
    const float* W_rel1  = (const float*)d_in[3];
    const float* W_root1 = (const float*)d_in[4];
    const float* b1      = (const float*)d_in[5];
    const float* W_rel2  = (const float*)d_in[6];
    const float* W_root2 = (const float*)d_in[7];
    const float* b2      = (const float*)d_in[8];
    const float* W_rel3  = (const float*)d_in[9];
    const float* W_root3 = (const float*)d_in[10];
    const float* b3      = (const float*)d_in[11];
    const float* We1     = (const float*)d_in[12];
    const float* be1     = (const float*)d_in[13];
    const float* We2     = (const float*)d_in[14];
    const float* be2     = (const float*)d_in[15];
    const float* Wn1     = (const float*)d_in[16];
    const float* bn1     = (const float*)d_in[17];
    const float* Wn2     = (const float*)d_in[18];
    const float* bn2     = (const float*)d_in[19];

    const int E = in_sizes[2];
    const int* src = ei;
    const int* dst = ei + E;

    bf16 *B1h, *B1l, *B2h, *B2l, *B3h, *B3l, *Weh, *Wel, *xh, *xl;
    float *hcomb;
    int *offs, *cur, *cnt3, *epack;
    cudaGetSymbolAddress((void**)&B1h, g_B1h);
    cudaGetSymbolAddress((void**)&B1l, g_B1l);
    cudaGetSymbolAddress((void**)&B2h, g_B2h);
    cudaGetSymbolAddress((void**)&B2l, g_B2l);
    cudaGetSymbolAddress((void**)&B3h, g_B3h);
    cudaGetSymbolAddress((void**)&B3l, g_B3l);
    cudaGetSymbolAddress((void**)&Weh, g_Weh);
    cudaGetSymbolAddress((void**)&Wel, g_Wel);
    cudaGetSymbolAddress((void**)&xh, g_xh);
    cudaGetSymbolAddress((void**)&xl, g_xl);
    cudaGetSymbolAddress((void**)&hcomb, g_hcomb);
    cudaGetSymbolAddress((void**)&offs, g_offs);
    cudaGetSymbolAddress((void**)&cur, g_cur);
    cudaGetSymbolAddress((void**)&cnt3, g_cnt3);
    cudaGetSymbolAddress((void**)&epack, g_epack);

    cudaFuncSetAttribute(gemm_mma, cudaFuncAttributeMaxDynamicSharedMemorySize, DYN_SMEM);

    float* out = (float*)d_out;
    float* edge_out = out;
    float* node_out = out + (size_t)E * 3;

    const int aggBlocks = (NN * 32 + 255) / 256;
    const int cntBlocks = (E + 255) / 256;
    const int edgeBlocks = (E * 32 + 255) / 256;
    const int nodeBlocks = (NN + 63) / 64;
    dim3 gemmGrid(4, (NN + 127) / 128);
    dim3 uvGrid(2, (NN + 127) / 128);

    // ---- upfront (fused): weight packs + edge counts + input split ----
    cudaMemsetAsync(cur, 0, NN * sizeof(int));
    cudaMemsetAsync(cnt3, 0, NN * RR * sizeof(int));
    prep_kernel<<<PACK_BLOCKS + cntBlocks + SPLIT_BLOCKS, 256>>>(
        W_root1, W_rel1, W_root2, W_rel2, W_root3, W_rel3, We1,
        B1h, B1l, B2h, B2l, B3h, B3l, Weh, Wel,
        dst, et, cnt3, E, cntBlocks, x, xh, xl);
    scan_kernel<<<1, 1024>>>(cnt3, offs);
    fill_kernel<<<cntBlocks, 256>>>(src, dst, et, offs, cur, epack, E);

    // ---- layer 1 ----
    gemm_mma<<<gemmGrid, 256, DYN_SMEM>>>(xh, xl, B1h, B1l, hcomb, NN, INF, 512);
    agg_combine<<<aggBlocks, 256>>>(hcomb, offs, epack, cnt3, b1, xh, xl, 1);

    // ---- layer 2 ----
    gemm_mma<<<gemmGrid, 256, DYN_SMEM>>>(xh, xl, B2h, B2l, hcomb, NN, HH, 512);
    agg_combine<<<aggBlocks, 256>>>(hcomb, offs, epack, cnt3, b2, xh, xl, 1);

    // ---- layer 3 (no relu) ----
    gemm_mma<<<gemmGrid, 256, DYN_SMEM>>>(xh, xl, B3h, B3l, hcomb, NN, HH, 512);
    agg_combine<<<aggBlocks, 256>>>(hcomb, offs, epack, cnt3, b3, xh, xl, 0);

    // ---- edge head UV GEMM, then fused tail (edge apply + node head) ----
    gemm_mma<<<uvGrid, 256, DYN_SMEM>>>(xh, xl, Weh, Wel, hcomb, NN, HH, 256);
    tail_kernel<<<edgeBlocks + nodeBlocks, 256>>>(
        hcomb, src, dst, be1, We2, be2, edge_out, E, edgeBlocks,
        xh, xl, Wn1, bn1, Wn2, bn2, node_out);
}

// round 14
// speedup vs baseline: 1.0424x; 1.0424x over previous
#include <cuda_runtime.h>
#include <cuda_bf16.h>
#include <cstdint>

// ---------------- problem constants ----------------
#define NN    50000
#define INF   768
#define HH    128
#define RR    3

typedef __nv_bfloat16 bf16;

// ---------------- scratch (device globals; no runtime alloc) ----------------
__device__ bf16  g_B1h[512 * INF];
__device__ bf16  g_B1l[512 * INF];
__device__ bf16  g_B2h[512 * HH];
__device__ bf16  g_B2l[512 * HH];
__device__ bf16  g_B3h[512 * HH];
__device__ bf16  g_B3l[512 * HH];
__device__ bf16  g_Weh[256 * 128];
__device__ bf16  g_Wel[256 * 128];
__device__ bf16  g_xh[(size_t)NN * INF];      // activation hi (bf16)
__device__ bf16  g_xl[(size_t)NN * INF];      // activation lo
__device__ float g_hcomb[(size_t)NN * 512];   // GEMM out [N,512]; reused as UV [N,256]
__device__ int   g_offs[NN + 1];
__device__ int   g_cur[NN];
__device__ int   g_cnt3[NN * RR];
__device__ int   g_epack[800000 + 64];        // CSR edge data: src | et<<28

// ================= helpers =================
__device__ __forceinline__ uint32_t smem_u32(const void* p) {
    uint32_t a;
    asm("{ .reg .u64 t; cvta.to.shared.u64 t, %1; cvt.u32.u64 %0, t; }" : "=r"(a) : "l"(p));
    return a;
}
// L2-only policy: staged tiles are consumed exactly once from smem.
__device__ __forceinline__ void cpasync16(uint32_t saddr, const void* g) {
    asm volatile("cp.async.cg.shared.global [%0], [%1], 16;" :: "r"(saddr), "l"(g));
}
#define CP_COMMIT() asm volatile("cp.async.commit_group;" ::: "memory")
#define CP_WAIT1()  asm volatile("cp.async.wait_group 1;" ::: "memory")
#define CP_WAIT0()  asm volatile("cp.async.wait_group 0;" ::: "memory")

__device__ __forceinline__ void ldsm4(uint32_t (&r)[4], uint32_t addr) {
    asm volatile("ldmatrix.sync.aligned.m8n8.x4.shared.b16 {%0,%1,%2,%3}, [%4];"
                 : "=r"(r[0]), "=r"(r[1]), "=r"(r[2]), "=r"(r[3]) : "r"(addr));
}
__device__ __forceinline__ void mma_bf16(float (&d)[4], const uint32_t (&a)[4],
                                         uint32_t b0, uint32_t b1) {
    asm volatile("mma.sync.aligned.m16n8k16.row.col.f32.bf16.bf16.f32 "
                 "{%0,%1,%2,%3}, {%4,%5,%6,%7}, {%8,%9}, {%0,%1,%2,%3};"
                 : "+f"(d[0]), "+f"(d[1]), "+f"(d[2]), "+f"(d[3])
                 : "r"(a[0]), "r"(a[1]), "r"(a[2]), "r"(a[3]), "r"(b0), "r"(b1));
}

// smem tile: 128 rows x 4 chunks of 16B. XOR swizzle.
__device__ __forceinline__ uint32_t swz(int row, int chunk) {
    return (uint32_t)(((row << 2) + (chunk ^ ((row >> 1) & 3))) << 4);
}
#define TILE_B  8192
#define STAGE_B (4 * TILE_B)
#define NSTAGE  3
#define DYN_SMEM (NSTAGE * STAGE_B)    // 96 KB

// ---------------- stage loader ----------------
__device__ __forceinline__ void load_stage_dense(
    uint32_t sb, const bf16* __restrict__ Ah, const bf16* __restrict__ Al,
    const bf16* __restrict__ Bh, const bf16* __restrict__ Bl,
    int K, int bm, int n0, int k0, int M, int tid) {
#pragma unroll
    for (int i = 0; i < 2; i++) {
        int cid = tid * 2 + i;
        int row = cid >> 2, ch = cid & 3;
        int gm = bm + row; if (gm >= M) gm = M - 1;
        size_t ga = (size_t)gm * K + k0 + ch * 8;
        uint32_t so = swz(row, ch);
        cpasync16(sb + so, Ah + ga);
        cpasync16(sb + TILE_B + so, Al + ga);
        size_t gb = (size_t)(n0 + row) * K + k0 + ch * 8;
        cpasync16(sb + 2 * TILE_B + so, Bh + gb);
        cpasync16(sb + 3 * TILE_B + so, Bl + gb);
    }
}

// ---------------- warp-tile compute (64x32, bf16x3) ----------------
__device__ __forceinline__ void compute_stage(float (&acc)[4][4][4], uint32_t sb,
                                              int m0w, int n0w, int lane) {
#pragma unroll
    for (int kf = 0; kf < 2; kf++) {
        uint32_t ah[4][4], al[4][4], bh[2][4], bl[2][4];
        const int arow = lane & 15;
        const int ach = kf * 2 + (lane >> 4);
        const int brow = n0w + ((lane >> 4) << 3) + (lane & 7);
        const int bch = kf * 2 + ((lane >> 3) & 1);
#pragma unroll
        for (int mf = 0; mf < 4; mf++)
            ldsm4(ah[mf], sb + swz(m0w + mf * 16 + arow, ach));
#pragma unroll
        for (int p = 0; p < 2; p++)
            ldsm4(bh[p], sb + 2 * TILE_B + swz(brow + p * 16, bch));
#pragma unroll
        for (int mf = 0; mf < 4; mf++)
#pragma unroll
            for (int nf = 0; nf < 4; nf++)
                mma_bf16(acc[mf][nf], ah[mf], bh[nf >> 1][(nf & 1) * 2], bh[nf >> 1][(nf & 1) * 2 + 1]);
#pragma unroll
        for (int p = 0; p < 2; p++)
            ldsm4(bl[p], sb + 3 * TILE_B + swz(brow + p * 16, bch));
#pragma unroll
        for (int mf = 0; mf < 4; mf++)
#pragma unroll
            for (int nf = 0; nf < 4; nf++)
                mma_bf16(acc[mf][nf], ah[mf], bl[nf >> 1][(nf & 1) * 2], bl[nf >> 1][(nf & 1) * 2 + 1]);
#pragma unroll
        for (int mf = 0; mf < 4; mf++)
            ldsm4(al[mf], sb + TILE_B + swz(m0w + mf * 16 + arow, ach));
#pragma unroll
        for (int mf = 0; mf < 4; mf++)
#pragma unroll
            for (int nf = 0; nf < 4; nf++)
                mma_bf16(acc[mf][nf], al[mf], bh[nf >> 1][(nf & 1) * 2], bh[nf >> 1][(nf & 1) * 2 + 1]);
    }
}

// ---------------- GEMM: 3-stage cp.async pipeline ----------------
__global__ __launch_bounds__(256)
void gemm_mma(const bf16* __restrict__ Ah, const bf16* __restrict__ Al,
              const bf16* __restrict__ Bh, const bf16* __restrict__ Bl,
              float* __restrict__ C, int M, int K, int ldc) {
    extern __shared__ char dsm[];
    const uint32_t sb = smem_u32(dsm);
    const int tid = threadIdx.x, lane = tid & 31, wid = tid >> 5;
    const int bm = blockIdx.y * 128, n0 = blockIdx.x * 128;
    const int m0w = (wid >> 2) * 64, n0w = (wid & 3) * 32;
    float acc[4][4][4];
#pragma unroll
    for (int a = 0; a < 4; a++)
#pragma unroll
        for (int b = 0; b < 4; b++)
#pragma unroll
            for (int c = 0; c < 4; c++) acc[a][b][c] = 0.f;

    const int niter = K / 32;   // always >= 2 here
    load_stage_dense(sb, Ah, Al, Bh, Bl, K, bm, n0, 0, M, tid);
    CP_COMMIT();
    load_stage_dense(sb + STAGE_B, Ah, Al, Bh, Bl, K, bm, n0, 32, M, tid);
    CP_COMMIT();

    int buf = 0;
    for (int it = 0; it < niter; it++) {
        if (it + 1 < niter) CP_WAIT1(); else CP_WAIT0();
        __syncthreads();
        if (it + 2 < niter) {
            int nb = buf + 2; if (nb >= NSTAGE) nb -= NSTAGE;
            load_stage_dense(sb + nb * STAGE_B, Ah, Al, Bh, Bl, K, bm, n0, (it + 2) * 32, M, tid);
            CP_COMMIT();
        }
        compute_stage(acc, sb + buf * STAGE_B, m0w, n0w, lane);
        if (++buf == NSTAGE) buf = 0;
    }

#pragma unroll
    for (int mf = 0; mf < 4; mf++) {
#pragma unroll
        for (int nf = 0; nf < 4; nf++) {
            int col = n0 + n0w + nf * 8 + (lane & 3) * 2;
            int r0 = bm + m0w + mf * 16 + (lane >> 2);
            if (r0 < M)
                *(float2*)&C[(size_t)r0 * ldc + col] = make_float2(acc[mf][nf][0], acc[mf][nf][1]);
            int r1 = r0 + 8;
            if (r1 < M)
                *(float2*)&C[(size_t)r1 * ldc + col] = make_float2(acc[mf][nf][2], acc[mf][nf][3]);
        }
    }
}

// ---------------- prep: pack_all + cnt + split fused via block-range dispatch ----------------
__device__ __forceinline__ void pack_one(float v, bf16* __restrict__ Bh,
                                         bf16* __restrict__ Bl, int idx) {
    bf16 h = __float2bfloat16(v);
    Bh[idx] = h;
    Bl[idx] = __float2bfloat16(v - __bfloat162float(h));
}
__device__ __forceinline__ float layer_w(const float* __restrict__ W_root,
                                         const float* __restrict__ W_rel,
                                         int idx, int K) {
    int n = idx / K, k = idx % K;
    if (n < HH) return W_root[k * HH + n];
    return W_rel[((size_t)((n >> 7) - 1) * K + k) * HH + (n & 127)];
}
#define P1 (512 * INF)
#define P2 (512 * HH)
#define PACK_TOTAL  (P1 + 2 * P2 + 256 * 128)
#define PACK_BLOCKS ((PACK_TOTAL + 255) / 256)
#define SPLIT_N4    (NN * INF / 4)
#define SPLIT_BLOCKS ((SPLIT_N4 + 255) / 256)

__global__ __launch_bounds__(256)
void prep_kernel(const float* __restrict__ Wr1, const float* __restrict__ Wrel1,
                 const float* __restrict__ Wr2, const float* __restrict__ Wrel2,
                 const float* __restrict__ Wr3, const float* __restrict__ Wrel3,
                 const float* __restrict__ We1,
                 bf16* B1h, bf16* B1l, bf16* B2h, bf16* B2l,
                 bf16* B3h, bf16* B3l, bf16* Weh, bf16* Wel,
                 const int* __restrict__ dst, const int* __restrict__ et,
                 int* __restrict__ cnt3, int E, int cntBlocks,
                 const float* __restrict__ x, bf16* __restrict__ xh, bf16* __restrict__ xl) {
    int blk = blockIdx.x;
    if (blk < PACK_BLOCKS) {
        int idx = blk * 256 + threadIdx.x;
        if (idx < P1) {
            pack_one(layer_w(Wr1, Wrel1, idx, INF), B1h, B1l, idx);
        } else if (idx < P1 + P2) {
            int i = idx - P1;
            pack_one(layer_w(Wr2, Wrel2, i, HH), B2h, B2l, i);
        } else if (idx < P1 + 2 * P2) {
            int i = idx - P1 - P2;
            pack_one(layer_w(Wr3, Wrel3, i, HH), B3h, B3l, i);
        } else if (idx < PACK_TOTAL) {
            int i = idx - P1 - 2 * P2;
            int n = i / 128, k = i % 128;
            float v = (n < 128) ? We1[k * 128 + n] : We1[(128 + k) * 128 + (n - 128)];
            pack_one(v, Weh, Wel, i);
        }
        return;
    }
    blk -= PACK_BLOCKS;
    if (blk < cntBlocks) {
        int i = blk * 256 + threadIdx.x;
        if (i < E) atomicAdd(&cnt3[dst[i] * RR + et[i]], 1);
        return;
    }
    blk -= cntBlocks;
    {
        int i = blk * 256 + threadIdx.x;
        if (i >= SPLIT_N4) return;
        float4 v = ((const float4*)x)[i];
        bf16 h0 = __float2bfloat16(v.x), h1 = __float2bfloat16(v.y);
        bf16 h2 = __float2bfloat16(v.z), h3 = __float2bfloat16(v.w);
        ((__nv_bfloat162*)xh)[i * 2]     = __nv_bfloat162(h0, h1);
        ((__nv_bfloat162*)xh)[i * 2 + 1] = __nv_bfloat162(h2, h3);
        ((__nv_bfloat162*)xl)[i * 2]     = __nv_bfloat162(__float2bfloat16(v.x - __bfloat162float(h0)),
                                                          __float2bfloat16(v.y - __bfloat162float(h1)));
        ((__nv_bfloat162*)xl)[i * 2 + 1] = __nv_bfloat162(__float2bfloat16(v.z - __bfloat162float(h2)),
                                                          __float2bfloat16(v.w - __bfloat162float(h3)));
    }
}

// ---------------- scan over cnt3 triplets -> offs ----------------
__global__ void scan_kernel(const int* __restrict__ cnt3, int* __restrict__ offs) {
    __shared__ int warp_sums[32];
    __shared__ int s_carry;
    const int t = threadIdx.x;          // 1024 threads, single block
    const int lane = t & 31, w = t >> 5;
    if (t == 0) { s_carry = 0; offs[0] = 0; }
    __syncthreads();
    for (int base = 0; base < NN; base += 1024) {
        int i = base + t;
        int v = 0;
        if (i < NN)
            v = cnt3[i * RR + 0] + cnt3[i * RR + 1] + cnt3[i * RR + 2];
        int x = v;
#pragma unroll
        for (int o = 1; o < 32; o <<= 1) {
            int y = __shfl_up_sync(0xFFFFFFFFu, x, o);
            if (lane >= o) x += y;
        }
        if (lane == 31) warp_sums[w] = x;
        __syncthreads();
        if (w == 0) {
            int s = warp_sums[lane];
#pragma unroll
            for (int o = 1; o < 32; o <<= 1) {
                int y = __shfl_up_sync(0xFFFFFFFFu, s, o);
                if (lane >= o) s += y;
            }
            warp_sums[lane] = s;
        }
        __syncthreads();
        int incl = x + (w > 0 ? warp_sums[w - 1] : 0) + s_carry;
        if (i < NN) offs[i + 1] = incl;
        __syncthreads();
        if (t == 1023) s_carry = incl;
        __syncthreads();
    }
}

__global__ void fill_kernel(const int* __restrict__ src, const int* __restrict__ dst,
                            const int* __restrict__ et, const int* __restrict__ offs,
                            int* __restrict__ cur, int* __restrict__ epack, int E) {
    int i = blockIdx.x * blockDim.x + threadIdx.x;
    if (i >= E) return;
    int d = dst[i];
    int p = atomicAdd(&cur[d], 1);
    epack[offs[d] + p] = src[i] | (et[i] << 28);
}

// ---------------- fused aggregation: warp/node, branch-free weighted sum ----------------
__global__ __launch_bounds__(256)
void agg_combine(const float* __restrict__ hcomb, const int* __restrict__ offs,
                 const int* __restrict__ epack, const int* __restrict__ cnt3,
                 const float* __restrict__ b,
                 bf16* __restrict__ xh, bf16* __restrict__ xl, int do_relu) {
    int node = (blockIdx.x * blockDim.x + threadIdx.x) >> 5;
    int lane = threadIdx.x & 31;
    if (node >= NN) return;
    const int o0 = offs[node], o1 = offs[node + 1];
    const float w0 = 1.f / (float)max(__ldg(&cnt3[node * RR + 0]), 1);
    const float w1 = 1.f / (float)max(__ldg(&cnt3[node * RR + 1]), 1);
    const float w2 = 1.f / (float)max(__ldg(&cnt3[node * RR + 2]), 1);

    float4 root = *(const float4*)&hcomb[(size_t)node * 512 + lane * 4];
    float4 bb = *(const float4*)&b[lane * 4];
    float tx = root.x + bb.x, ty = root.y + bb.y;
    float tz = root.z + bb.z, tw = root.w + bb.w;

    const float* __restrict__ hb = hcomb + 128 + lane * 4;
    int e = o0;
    for (; e + 4 <= o1; e += 4) {
        int p0 = __ldg(&epack[e + 0]);
        int p1 = __ldg(&epack[e + 1]);
        int p2 = __ldg(&epack[e + 2]);
        int p3 = __ldg(&epack[e + 3]);
        int r0 = (unsigned)p0 >> 28, r1 = (unsigned)p1 >> 28;
        int r2 = (unsigned)p2 >> 28, r3 = (unsigned)p3 >> 28;
        float4 v0 = __ldg((const float4*)(hb + ((size_t)(p0 & 0x0FFFFFFF) * 512 + (r0 << 7))));
        float4 v1 = __ldg((const float4*)(hb + ((size_t)(p1 & 0x0FFFFFFF) * 512 + (r1 << 7))));
        float4 v2 = __ldg((const float4*)(hb + ((size_t)(p2 & 0x0FFFFFFF) * 512 + (r2 << 7))));
        float4 v3 = __ldg((const float4*)(hb + ((size_t)(p3 & 0x0FFFFFFF) * 512 + (r3 << 7))));
        float ws0 = (r0 == 0) ? w0 : ((r0 == 1) ? w1 : w2);
        float ws1 = (r1 == 0) ? w0 : ((r1 == 1) ? w1 : w2);
        float ws2 = (r2 == 0) ? w0 : ((r2 == 1) ? w1 : w2);
        float ws3 = (r3 == 0) ? w0 : ((r3 == 1) ? w1 : w2);
        tx += v0.x * ws0 + v1.x * ws1 + v2.x * ws2 + v3.x * ws3;
        ty += v0.y * ws0 + v1.y * ws1 + v2.y * ws2 + v3.y * ws3;
        tz += v0.z * ws0 + v1.z * ws1 + v2.z * ws2 + v3.z * ws3;
        tw += v0.w * ws0 + v1.w * ws1 + v2.w * ws2 + v3.w * ws3;
    }
    if (e + 2 <= o1) {
        int p0 = __ldg(&epack[e + 0]);
        int p1 = __ldg(&epack[e + 1]);
        int r0 = (unsigned)p0 >> 28, r1 = (unsigned)p1 >> 28;
        float4 v0 = __ldg((const float4*)(hb + ((size_t)(p0 & 0x0FFFFFFF) * 512 + (r0 << 7))));
        float4 v1 = __ldg((const float4*)(hb + ((size_t)(p1 & 0x0FFFFFFF) * 512 + (r1 << 7))));
        float ws0 = (r0 == 0) ? w0 : ((r0 == 1) ? w1 : w2);
        float ws1 = (r1 == 0) ? w0 : ((r1 == 1) ? w1 : w2);
        tx += v0.x * ws0 + v1.x * ws1;
        ty += v0.y * ws0 + v1.y * ws1;
        tz += v0.z * ws0 + v1.z * ws1;
        tw += v0.w * ws0 + v1.w * ws1;
        e += 2;
    }
    if (e < o1) {
        int p0 = __ldg(&epack[e]);
        int r0 = (unsigned)p0 >> 28;
        float4 v0 = __ldg((const float4*)(hb + ((size_t)(p0 & 0x0FFFFFFF) * 512 + (r0 << 7))));
        float ws0 = (r0 == 0) ? w0 : ((r0 == 1) ? w1 : w2);
        tx += v0.x * ws0; ty += v0.y * ws0; tz += v0.z * ws0; tw += v0.w * ws0;
    }

    if (do_relu) {
        tx = fmaxf(tx, 0.f); ty = fmaxf(ty, 0.f);
        tz = fmaxf(tz, 0.f); tw = fmaxf(tw, 0.f);
    }
    size_t idx = (size_t)node * HH + lane * 4;
    bf16 h0 = __float2bfloat16(tx), h1 = __float2bfloat16(ty);
    bf16 h2 = __float2bfloat16(tz), h3 = __float2bfloat16(tw);
    __nv_bfloat162 hh0(h0, h1), hh1(h2, h3);
    *(uint2*)&xh[idx] = make_uint2(*(uint32_t*)&hh0, *(uint32_t*)&hh1);
    __nv_bfloat162 ll0(__float2bfloat16(tx - __bfloat162float(h0)),
                       __float2bfloat16(ty - __bfloat162float(h1)));
    __nv_bfloat162 ll1(__float2bfloat16(tz - __bfloat162float(h2)),
                       __float2bfloat16(tw - __bfloat162float(h3)));
    *(uint2*)&xl[idx] = make_uint2(*(uint32_t*)&ll0, *(uint32_t*)&ll1);
}

// ---------------- edge apply: warp/edge, relu(U[src]+V[dst]+be1) @ We2 + be2 ----------------
__global__ __launch_bounds__(256)
void edge_apply(const float* __restrict__ UV,
                const int* __restrict__ src, const int* __restrict__ dst,
                const float* __restrict__ be1, const float* __restrict__ We2,
                const float* __restrict__ be2, float* __restrict__ out, int E) {
    __shared__ float sBe1[128];
    __shared__ float sW2[384];
    const int tid = threadIdx.x, lane = tid & 31;
    if (tid < 128) sBe1[tid] = be1[tid];
    for (int v = tid; v < 384; v += 256) sW2[v] = We2[v];
    __syncthreads();
    int gw = (blockIdx.x * 256 + tid) >> 5;
    if (gw >= E) return;
    int s = src[gw], d = dst[gw];
    float4 u = __ldg((const float4*)(UV + (size_t)s * 256 + lane * 4));
    float4 v = __ldg((const float4*)(UV + (size_t)d * 256 + 128 + lane * 4));
    int c = lane * 4;
    float a0 = 0.f, a1 = 0.f, a2 = 0.f;
    float h;
    h = fmaxf(u.x + v.x + sBe1[c + 0], 0.f); a0 += h * sW2[(c + 0) * 3]; a1 += h * sW2[(c + 0) * 3 + 1]; a2 += h * sW2[(c + 0) * 3 + 2];
    h = fmaxf(u.y + v.y + sBe1[c + 1], 0.f); a0 += h * sW2[(c + 1) * 3]; a1 += h * sW2[(c + 1) * 3 + 1]; a2 += h * sW2[(c + 1) * 3 + 2];
    h = fmaxf(u.z + v.z + sBe1[c + 2], 0.f); a0 += h * sW2[(c + 2) * 3]; a1 += h * sW2[(c + 2) * 3 + 1]; a2 += h * sW2[(c + 2) * 3 + 2];
    h = fmaxf(u.w + v.w + sBe1[c + 3], 0.f); a0 += h * sW2[(c + 3) * 3]; a1 += h * sW2[(c + 3) * 3 + 1]; a2 += h * sW2[(c + 3) * 3 + 2];
#pragma unroll
    for (int o = 16; o; o >>= 1) {
        a0 += __shfl_xor_sync(0xFFFFFFFFu, a0, o);
        a1 += __shfl_xor_sync(0xFFFFFFFFu, a1, o);
        a2 += __shfl_xor_sync(0xFFFFFFFFu, a2, o);
    }
    if (lane == 0) {
        out[(size_t)gw * 3 + 0] = a0 + __ldg(&be2[0]);
        out[(size_t)gw * 3 + 1] = a1 + __ldg(&be2[1]);
        out[(size_t)gw * 3 + 2] = a2 + __ldg(&be2[2]);
    }
}

// ---------------- node head: 64 nodes/block; x3 reconstructed from xh+xl ----------------
__global__ __launch_bounds__(256)
void node_head_kernel(const bf16* __restrict__ xh, const bf16* __restrict__ xl,
                      const float* __restrict__ Wn1, const float* __restrict__ bn1,
                      const float* __restrict__ Wn2, const float* __restrict__ bn2,
                      float* __restrict__ out) {
    __shared__ float sW1[128 * 64];
    __shared__ float sb1[64];
    __shared__ float sW2[128];
    __shared__ float sx[4][128];
    __shared__ float sPart[8][2];
    const int tid = threadIdx.x;
    const int team = tid >> 6, t = tid & 63;      // 4 teams of 64
    const int wid = tid >> 5, lane = tid & 31;
    for (int i = tid; i < 128 * 64; i += 256) sW1[i] = Wn1[i];
    if (tid < 64) sb1[tid] = bn1[tid];
    if (tid < 128) sW2[tid] = Wn2[tid];
    float b20 = __ldg(&bn2[0]), b21 = __ldg(&bn2[1]);
    __syncthreads();
    const int base = blockIdx.x * 64;
#pragma unroll 1
    for (int it = 0; it < 16; it++) {
        int node = base + it * 4 + team;
        bool ok = node < NN;
        if (ok) {
            size_t off = (size_t)node * HH;
            sx[team][t]      = __bfloat162float(xh[off + t])      + __bfloat162float(xl[off + t]);
            sx[team][t + 64] = __bfloat162float(xh[off + t + 64]) + __bfloat162float(xl[off + t + 64]);
        }
        __syncthreads();
        float p0 = 0.f, p1 = 0.f;
        if (ok) {
            float acc = sb1[t];
#pragma unroll
            for (int k = 0; k < 128; k++) acc += sx[team][k] * sW1[k * 64 + t];
            float hgt = fmaxf(acc, 0.f);
            p0 = hgt * sW2[t * 2 + 0];
            p1 = hgt * sW2[t * 2 + 1];
        }
#pragma unroll
        for (int o = 16; o; o >>= 1) {
            p0 += __shfl_xor_sync(0xFFFFFFFFu, p0, o);
            p1 += __shfl_xor_sync(0xFFFFFFFFu, p1, o);
        }
        if (lane == 0) { sPart[wid][0] = p0; sPart[wid][1] = p1; }
        __syncthreads();
        if (ok && t == 0) {
            out[(size_t)node * 2 + 0] = sPart[team * 2][0] + sPart[team * 2 + 1][0] + b20;
            out[(size_t)node * 2 + 1] = sPart[team * 2][1] + sPart[team * 2 + 1][1] + b21;
        }
        __syncthreads();
    }
}

// ---------------- launch ----------------
extern "C" void kernel_launch(void* const* d_in, const int* in_sizes, int n_in,
                              void* d_out, int out_size) {
    const float* x       = (const float*)d_in[0];
    const int*   ei      = (const int*)d_in[1];
    const int*   et      = (const int*)d_in[2];
    const float* W_rel1  = (const float*)d_in[3];
    const float* W_root1 = (const float*)d_in[4];
    const float* b1      = (const float*)d_in[5];
    const float* W_rel2  = (const float*)d_in[6];
    const float* W_root2 = (const float*)d_in[7];
    const float* b2      = (const float*)d_in[8];
    const float* W_rel3  = (const float*)d_in[9];
    const float* W_root3 = (const float*)d_in[10];
    const float* b3      = (const float*)d_in[11];
    const float* We1     = (const float*)d_in[12];
    const float* be1     = (const float*)d_in[13];
    const float* We2     = (const float*)d_in[14];
    const float* be2     = (const float*)d_in[15];
    const float* Wn1     = (const float*)d_in[16];
    const float* bn1     = (const float*)d_in[17];
    const float* Wn2     = (const float*)d_in[18];
    const float* bn2     = (const float*)d_in[19];

    const int E = in_sizes[2];
    const int* src = ei;
    const int* dst = ei + E;

    bf16 *B1h, *B1l, *B2h, *B2l, *B3h, *B3l, *Weh, *Wel, *xh, *xl;
    float *hcomb;
    int *offs, *cur, *cnt3, *epack;
    cudaGetSymbolAddress((void**)&B1h, g_B1h);
    cudaGetSymbolAddress((void**)&B1l, g_B1l);
    cudaGetSymbolAddress((void**)&B2h, g_B2h);
    cudaGetSymbolAddress((void**)&B2l, g_B2l);
    cudaGetSymbolAddress((void**)&B3h, g_B3h);
    cudaGetSymbolAddress((void**)&B3l, g_B3l);
    cudaGetSymbolAddress((void**)&Weh, g_Weh);
    cudaGetSymbolAddress((void**)&Wel, g_Wel);
    cudaGetSymbolAddress((void**)&xh, g_xh);
    cudaGetSymbolAddress((void**)&xl, g_xl);
    cudaGetSymbolAddress((void**)&hcomb, g_hcomb);
    cudaGetSymbolAddress((void**)&offs, g_offs);
    cudaGetSymbolAddress((void**)&cur, g_cur);
    cudaGetSymbolAddress((void**)&cnt3, g_cnt3);
    cudaGetSymbolAddress((void**)&epack, g_epack);

    cudaFuncSetAttribute(gemm_mma, cudaFuncAttributeMaxDynamicSharedMemorySize, DYN_SMEM);

    float* out = (float*)d_out;
    float* edge_out = out;
    float* node_out = out + (size_t)E * 3;

    const int aggBlocks = (NN * 32 + 255) / 256;
    const int cntBlocks = (E + 255) / 256;
    dim3 gemmGrid(4, (NN + 127) / 128);
    dim3 uvGrid(2, (NN + 127) / 128);

    // ---- upfront (fused): weight packs + edge counts + input split ----
    cudaMemsetAsync(cur, 0, NN * sizeof(int));
    cudaMemsetAsync(cnt3, 0, NN * RR * sizeof(int));
    prep_kernel<<<PACK_BLOCKS + cntBlocks + SPLIT_BLOCKS, 256>>>(
        W_root1, W_rel1, W_root2, W_rel2, W_root3, W_rel3, We1,
        B1h, B1l, B2h, B2l, B3h, B3l, Weh, Wel,
        dst, et, cnt3, E, cntBlocks, x, xh, xl);
    scan_kernel<<<1, 1024>>>(cnt3, offs);
    fill_kernel<<<cntBlocks, 256>>>(src, dst, et, offs, cur, epack, E);

    // ---- layer 1 ----
    gemm_mma<<<gemmGrid, 256, DYN_SMEM>>>(xh, xl, B1h, B1l, hcomb, NN, INF, 512);
    agg_combine<<<aggBlocks, 256>>>(hcomb, offs, epack, cnt3, b1, xh, xl, 1);

    // ---- layer 2 ----
    gemm_mma<<<gemmGrid, 256, DYN_SMEM>>>(xh, xl, B2h, B2l, hcomb, NN, HH, 512);
    agg_combine<<<aggBlocks, 256>>>(hcomb, offs, epack, cnt3, b2, xh, xl, 1);

    // ---- layer 3 (no relu) ----
    gemm_mma<<<gemmGrid, 256, DYN_SMEM>>>(xh, xl, B3h, B3l, hcomb, NN, HH, 512);
    agg_combine<<<aggBlocks, 256>>>(hcomb, offs, epack, cnt3, b3, xh, xl, 0);

    // ---- edge head: UV GEMM, then per-edge apply ----
    gemm_mma<<<uvGrid, 256, DYN_SMEM>>>(xh, xl, Weh, Wel, hcomb, NN, HH, 256);
    edge_apply<<<(E * 32 + 255) / 256, 256>>>(hcomb, src, dst, be1, We2, be2, edge_out, E);

    // ---- node head ----
    node_head_kernel<<<(NN + 63) / 64, 256>>>(xh, xl, Wn1, bn1, Wn2, bn2, node_out);
}

// round 15
// speedup vs baseline: 1.0746x; 1.0308x over previous
#include <cuda_runtime.h>
#include <cuda_bf16.h>
#include <cstdint>

// ---------------- problem constants ----------------
#define NN    50000
#define INF   768
#define HH    128
#define RR    3

typedef __nv_bfloat16 bf16;

// ---------------- scratch (device globals; no runtime alloc) ----------------
__device__ bf16  g_B1h[512 * INF];
__device__ bf16  g_B1l[512 * INF];
__device__ bf16  g_B2h[512 * HH];
__device__ bf16  g_B2l[512 * HH];
__device__ bf16  g_B3h[512 * HH];
__device__ bf16  g_B3l[512 * HH];
__device__ bf16  g_Weh[256 * 128];
__device__ bf16  g_Wel[256 * 128];
__device__ bf16  g_xh[(size_t)NN * INF];      // activation hi (bf16)
__device__ bf16  g_xl[(size_t)NN * INF];      // activation lo
__device__ float g_hcomb[(size_t)NN * 512];   // GEMM out [N,512]; reused as UV [N,256]
__device__ int   g_offs[NN + 1];
__device__ int   g_cur[NN];
__device__ int   g_cnt3[NN * RR];
__device__ int   g_epack[800000 + 64];        // CSR edge data: src | et<<28

// ================= helpers =================
__device__ __forceinline__ uint32_t smem_u32(const void* p) {
    uint32_t a;
    asm("{ .reg .u64 t; cvta.to.shared.u64 t, %1; cvt.u32.u64 %0, t; }" : "=r"(a) : "l"(p));
    return a;
}
// L2-only policy: staged tiles are consumed exactly once from smem.
__device__ __forceinline__ void cpasync16(uint32_t saddr, const void* g) {
    asm volatile("cp.async.cg.shared.global [%0], [%1], 16;" :: "r"(saddr), "l"(g));
}
#define CP_COMMIT() asm volatile("cp.async.commit_group;" ::: "memory")
#define CP_WAIT1()  asm volatile("cp.async.wait_group 1;" ::: "memory")
#define CP_WAIT0()  asm volatile("cp.async.wait_group 0;" ::: "memory")

__device__ __forceinline__ void ldsm4(uint32_t (&r)[4], uint32_t addr) {
    asm volatile("ldmatrix.sync.aligned.m8n8.x4.shared.b16 {%0,%1,%2,%3}, [%4];"
                 : "=r"(r[0]), "=r"(r[1]), "=r"(r[2]), "=r"(r[3]) : "r"(addr));
}
__device__ __forceinline__ void mma_bf16(float (&d)[4], const uint32_t (&a)[4],
                                         uint32_t b0, uint32_t b1) {
    asm volatile("mma.sync.aligned.m16n8k16.row.col.f32.bf16.bf16.f32 "
                 "{%0,%1,%2,%3}, {%4,%5,%6,%7}, {%8,%9}, {%0,%1,%2,%3};"
                 : "+f"(d[0]), "+f"(d[1]), "+f"(d[2]), "+f"(d[3])
                 : "r"(a[0]), "r"(a[1]), "r"(a[2]), "r"(a[3]), "r"(b0), "r"(b1));
}

// smem tile: 128 rows x 4 chunks of 16B. XOR swizzle.
__device__ __forceinline__ uint32_t swz(int row, int chunk) {
    return (uint32_t)(((row << 2) + (chunk ^ ((row >> 1) & 3))) << 4);
}
#define TILE_B  8192
#define STAGE_B (4 * TILE_B)
#define NSTAGE  3
#define DYN_SMEM (NSTAGE * STAGE_B)    // 96 KB

// ---------------- stage loader ----------------
__device__ __forceinline__ void load_stage_dense(
    uint32_t sb, const bf16* __restrict__ Ah, const bf16* __restrict__ Al,
    const bf16* __restrict__ Bh, const bf16* __restrict__ Bl,
    int K, int bm, int n0, int k0, int M, int tid) {
#pragma unroll
    for (int i = 0; i < 2; i++) {
        int cid = tid * 2 + i;
        int row = cid >> 2, ch = cid & 3;
        int gm = bm + row; if (gm >= M) gm = M - 1;
        size_t ga = (size_t)gm * K + k0 + ch * 8;
        uint32_t so = swz(row, ch);
        cpasync16(sb + so, Ah + ga);
        cpasync16(sb + TILE_B + so, Al + ga);
        size_t gb = (size_t)(n0 + row) * K + k0 + ch * 8;
        cpasync16(sb + 2 * TILE_B + so, Bh + gb);
        cpasync16(sb + 3 * TILE_B + so, Bl + gb);
    }
}

// ---------------- warp-tile compute (64x32, bf16x3) ----------------
__device__ __forceinline__ void compute_stage(float (&acc)[4][4][4], uint32_t sb,
                                              int m0w, int n0w, int lane) {
#pragma unroll
    for (int kf = 0; kf < 2; kf++) {
        uint32_t ah[4][4], al[4][4], bh[2][4], bl[2][4];
        const int arow = lane & 15;
        const int ach = kf * 2 + (lane >> 4);
        const int brow = n0w + ((lane >> 4) << 3) + (lane & 7);
        const int bch = kf * 2 + ((lane >> 3) & 1);
#pragma unroll
        for (int mf = 0; mf < 4; mf++)
            ldsm4(ah[mf], sb + swz(m0w + mf * 16 + arow, ach));
#pragma unroll
        for (int p = 0; p < 2; p++)
            ldsm4(bh[p], sb + 2 * TILE_B + swz(brow + p * 16, bch));
#pragma unroll
        for (int mf = 0; mf < 4; mf++)
#pragma unroll
            for (int nf = 0; nf < 4; nf++)
                mma_bf16(acc[mf][nf], ah[mf], bh[nf >> 1][(nf & 1) * 2], bh[nf >> 1][(nf & 1) * 2 + 1]);
#pragma unroll
        for (int p = 0; p < 2; p++)
            ldsm4(bl[p], sb + 3 * TILE_B + swz(brow + p * 16, bch));
#pragma unroll
        for (int mf = 0; mf < 4; mf++)
#pragma unroll
            for (int nf = 0; nf < 4; nf++)
                mma_bf16(acc[mf][nf], ah[mf], bl[nf >> 1][(nf & 1) * 2], bl[nf >> 1][(nf & 1) * 2 + 1]);
#pragma unroll
        for (int mf = 0; mf < 4; mf++)
            ldsm4(al[mf], sb + TILE_B + swz(m0w + mf * 16 + arow, ach));
#pragma unroll
        for (int mf = 0; mf < 4; mf++)
#pragma unroll
            for (int nf = 0; nf < 4; nf++)
                mma_bf16(acc[mf][nf], al[mf], bh[nf >> 1][(nf & 1) * 2], bh[nf >> 1][(nf & 1) * 2 + 1]);
    }
}

// ---------------- GEMM: 3-stage cp.async pipeline ----------------
__global__ __launch_bounds__(256)
void gemm_mma(const bf16* __restrict__ Ah, const bf16* __restrict__ Al,
              const bf16* __restrict__ Bh, const bf16* __restrict__ Bl,
              float* __restrict__ C, int M, int K, int ldc) {
    extern __shared__ char dsm[];
    const uint32_t sb = smem_u32(dsm);
    const int tid = threadIdx.x, lane = tid & 31, wid = tid >> 5;
    const int bm = blockIdx.y * 128, n0 = blockIdx.x * 128;
    const int m0w = (wid >> 2) * 64, n0w = (wid & 3) * 32;
    float acc[4][4][4];
#pragma unroll
    for (int a = 0; a < 4; a++)
#pragma unroll
        for (int b = 0; b < 4; b++)
#pragma unroll
            for (int c = 0; c < 4; c++) acc[a][b][c] = 0.f;

    const int niter = K / 32;   // always >= 2 here
    load_stage_dense(sb, Ah, Al, Bh, Bl, K, bm, n0, 0, M, tid);
    CP_COMMIT();
    load_stage_dense(sb + STAGE_B, Ah, Al, Bh, Bl, K, bm, n0, 32, M, tid);
    CP_COMMIT();

    int buf = 0;
    for (int it = 0; it < niter; it++) {
        if (it + 1 < niter) CP_WAIT1(); else CP_WAIT0();
        __syncthreads();
        if (it + 2 < niter) {
            int nb = buf + 2; if (nb >= NSTAGE) nb -= NSTAGE;
            load_stage_dense(sb + nb * STAGE_B, Ah, Al, Bh, Bl, K, bm, n0, (it + 2) * 32, M, tid);
            CP_COMMIT();
        }
        compute_stage(acc, sb + buf * STAGE_B, m0w, n0w, lane);
        if (++buf == NSTAGE) buf = 0;
    }

#pragma unroll
    for (int mf = 0; mf < 4; mf++) {
#pragma unroll
        for (int nf = 0; nf < 4; nf++) {
            int col = n0 + n0w + nf * 8 + (lane & 3) * 2;
            int r0 = bm + m0w + mf * 16 + (lane >> 2);
            if (r0 < M)
                *(float2*)&C[(size_t)r0 * ldc + col] = make_float2(acc[mf][nf][0], acc[mf][nf][1]);
            int r1 = r0 + 8;
            if (r1 < M)
                *(float2*)&C[(size_t)r1 * ldc + col] = make_float2(acc[mf][nf][2], acc[mf][nf][3]);
        }
    }
}

// ---------------- prep: pack_all + cnt + split fused via block-range dispatch ----------------
__device__ __forceinline__ void pack_one(float v, bf16* __restrict__ Bh,
                                         bf16* __restrict__ Bl, int idx) {
    bf16 h = __float2bfloat16(v);
    Bh[idx] = h;
    Bl[idx] = __float2bfloat16(v - __bfloat162float(h));
}
__device__ __forceinline__ float layer_w(const float* __restrict__ W_root,
                                         const float* __restrict__ W_rel,
                                         int idx, int K) {
    int n = idx / K, k = idx % K;
    if (n < HH) return W_root[k * HH + n];
    return W_rel[((size_t)((n >> 7) - 1) * K + k) * HH + (n & 127)];
}
#define P1 (512 * INF)
#define P2 (512 * HH)
#define PACK_TOTAL  (P1 + 2 * P2 + 256 * 128)
#define PACK_BLOCKS ((PACK_TOTAL + 255) / 256)
#define SPLIT_N4    (NN * INF / 4)
#define SPLIT_BLOCKS ((SPLIT_N4 + 255) / 256)

__global__ __launch_bounds__(256)
void prep_kernel(const float* __restrict__ Wr1, const float* __restrict__ Wrel1,
                 const float* __restrict__ Wr2, const float* __restrict__ Wrel2,
                 const float* __restrict__ Wr3, const float* __restrict__ Wrel3,
                 const float* __restrict__ We1,
                 bf16* B1h, bf16* B1l, bf16* B2h, bf16* B2l,
                 bf16* B3h, bf16* B3l, bf16* Weh, bf16* Wel,
                 const int* __restrict__ dst, const int* __restrict__ et,
                 int* __restrict__ cnt3, int E, int cntBlocks,
                 const float* __restrict__ x, bf16* __restrict__ xh, bf16* __restrict__ xl) {
    int blk = blockIdx.x;
    if (blk < PACK_BLOCKS) {
        int idx = blk * 256 + threadIdx.x;
        if (idx < P1) {
            pack_one(layer_w(Wr1, Wrel1, idx, INF), B1h, B1l, idx);
        } else if (idx < P1 + P2) {
            int i = idx - P1;
            pack_one(layer_w(Wr2, Wrel2, i, HH), B2h, B2l, i);
        } else if (idx < P1 + 2 * P2) {
            int i = idx - P1 - P2;
            pack_one(layer_w(Wr3, Wrel3, i, HH), B3h, B3l, i);
        } else if (idx < PACK_TOTAL) {
            int i = idx - P1 - 2 * P2;
            int n = i / 128, k = i % 128;
            float v = (n < 128) ? We1[k * 128 + n] : We1[(128 + k) * 128 + (n - 128)];
            pack_one(v, Weh, Wel, i);
        }
        return;
    }
    blk -= PACK_BLOCKS;
    if (blk < cntBlocks) {
        int i = blk * 256 + threadIdx.x;
        if (i < E) atomicAdd(&cnt3[dst[i] * RR + et[i]], 1);
        return;
    }
    blk -= cntBlocks;
    {
        int i = blk * 256 + threadIdx.x;
        if (i >= SPLIT_N4) return;
        float4 v = ((const float4*)x)[i];
        bf16 h0 = __float2bfloat16(v.x), h1 = __float2bfloat16(v.y);
        bf16 h2 = __float2bfloat16(v.z), h3 = __float2bfloat16(v.w);
        ((__nv_bfloat162*)xh)[i * 2]     = __nv_bfloat162(h0, h1);
        ((__nv_bfloat162*)xh)[i * 2 + 1] = __nv_bfloat162(h2, h3);
        ((__nv_bfloat162*)xl)[i * 2]     = __nv_bfloat162(__float2bfloat16(v.x - __bfloat162float(h0)),
                                                          __float2bfloat16(v.y - __bfloat162float(h1)));
        ((__nv_bfloat162*)xl)[i * 2 + 1] = __nv_bfloat162(__float2bfloat16(v.z - __bfloat162float(h2)),
                                                          __float2bfloat16(v.w - __bfloat162float(h3)));
    }
}

// ---------------- scan over cnt3 triplets -> offs ----------------
__global__ void scan_kernel(const int* __restrict__ cnt3, int* __restrict__ offs) {
    __shared__ int warp_sums[32];
    __shared__ int s_carry;
    const int t = threadIdx.x;          // 1024 threads, single block
    const int lane = t & 31, w = t >> 5;
    if (t == 0) { s_carry = 0; offs[0] = 0; }
    __syncthreads();
    for (int base = 0; base < NN; base += 1024) {
        int i = base + t;
        int v = 0;
        if (i < NN)
            v = cnt3[i * RR + 0] + cnt3[i * RR + 1] + cnt3[i * RR + 2];
        int x = v;
#pragma unroll
        for (int o = 1; o < 32; o <<= 1) {
            int y = __shfl_up_sync(0xFFFFFFFFu, x, o);
            if (lane >= o) x += y;
        }
        if (lane == 31) warp_sums[w] = x;
        __syncthreads();
        if (w == 0) {
            int s = warp_sums[lane];
#pragma unroll
            for (int o = 1; o < 32; o <<= 1) {
                int y = __shfl_up_sync(0xFFFFFFFFu, s, o);
                if (lane >= o) s += y;
            }
            warp_sums[lane] = s;
        }
        __syncthreads();
        int incl = x + (w > 0 ? warp_sums[w - 1] : 0) + s_carry;
        if (i < NN) offs[i + 1] = incl;
        __syncthreads();
        if (t == 1023) s_carry = incl;
        __syncthreads();
    }
}

__global__ void fill_kernel(const int* __restrict__ src, const int* __restrict__ dst,
                            const int* __restrict__ et, const int* __restrict__ offs,
                            int* __restrict__ cur, int* __restrict__ epack, int E) {
    int i = blockIdx.x * blockDim.x + threadIdx.x;
    if (i >= E) return;
    int d = dst[i];
    int p = atomicAdd(&cur[d], 1);
    epack[offs[d] + p] = src[i] | (et[i] << 28);
}

// ---------------- fused aggregation: warp/node, branch-free weighted sum ----------------
__global__ __launch_bounds__(256)
void agg_combine(const float* __restrict__ hcomb, const int* __restrict__ offs,
                 const int* __restrict__ epack, const int* __restrict__ cnt3,
                 const float* __restrict__ b,
                 bf16* __restrict__ xh, bf16* __restrict__ xl, int do_relu) {
    int node = (blockIdx.x * blockDim.x + threadIdx.x) >> 5;
    int lane = threadIdx.x & 31;
    if (node >= NN) return;
    const int o0 = offs[node], o1 = offs[node + 1];
    const float w0 = 1.f / (float)max(__ldg(&cnt3[node * RR + 0]), 1);
    const float w1 = 1.f / (float)max(__ldg(&cnt3[node * RR + 1]), 1);
    const float w2 = 1.f / (float)max(__ldg(&cnt3[node * RR + 2]), 1);

    float4 root = *(const float4*)&hcomb[(size_t)node * 512 + lane * 4];
    float4 bb = *(const float4*)&b[lane * 4];
    float tx = root.x + bb.x, ty = root.y + bb.y;
    float tz = root.z + bb.z, tw = root.w + bb.w;

    const float* __restrict__ hb = hcomb + 128 + lane * 4;
    int e = o0;
    for (; e + 4 <= o1; e += 4) {
        int p0 = __ldg(&epack[e + 0]);
        int p1 = __ldg(&epack[e + 1]);
        int p2 = __ldg(&epack[e + 2]);
        int p3 = __ldg(&epack[e + 3]);
        int r0 = (unsigned)p0 >> 28, r1 = (unsigned)p1 >> 28;
        int r2 = (unsigned)p2 >> 28, r3 = (unsigned)p3 >> 28;
        float4 v0 = __ldg((const float4*)(hb + ((size_t)(p0 & 0x0FFFFFFF) * 512 + (r0 << 7))));
        float4 v1 = __ldg((const float4*)(hb + ((size_t)(p1 & 0x0FFFFFFF) * 512 + (r1 << 7))));
        float4 v2 = __ldg((const float4*)(hb + ((size_t)(p2 & 0x0FFFFFFF) * 512 + (r2 << 7))));
        float4 v3 = __ldg((const float4*)(hb + ((size_t)(p3 & 0x0FFFFFFF) * 512 + (r3 << 7))));
        float ws0 = (r0 == 0) ? w0 : ((r0 == 1) ? w1 : w2);
        float ws1 = (r1 == 0) ? w0 : ((r1 == 1) ? w1 : w2);
        float ws2 = (r2 == 0) ? w0 : ((r2 == 1) ? w1 : w2);
        float ws3 = (r3 == 0) ? w0 : ((r3 == 1) ? w1 : w2);
        tx += v0.x * ws0 + v1.x * ws1 + v2.x * ws2 + v3.x * ws3;
        ty += v0.y * ws0 + v1.y * ws1 + v2.y * ws2 + v3.y * ws3;
        tz += v0.z * ws0 + v1.z * ws1 + v2.z * ws2 + v3.z * ws3;
        tw += v0.w * ws0 + v1.w * ws1 + v2.w * ws2 + v3.w * ws3;
    }
    if (e + 2 <= o1) {
        int p0 = __ldg(&epack[e + 0]);
        int p1 = __ldg(&epack[e + 1]);
        int r0 = (unsigned)p0 >> 28, r1 = (unsigned)p1 >> 28;
        float4 v0 = __ldg((const float4*)(hb + ((size_t)(p0 & 0x0FFFFFFF) * 512 + (r0 << 7))));
        float4 v1 = __ldg((const float4*)(hb + ((size_t)(p1 & 0x0FFFFFFF) * 512 + (r1 << 7))));
        float ws0 = (r0 == 0) ? w0 : ((r0 == 1) ? w1 : w2);
        float ws1 = (r1 == 0) ? w0 : ((r1 == 1) ? w1 : w2);
        tx += v0.x * ws0 + v1.x * ws1;
        ty += v0.y * ws0 + v1.y * ws1;
        tz += v0.z * ws0 + v1.z * ws1;
        tw += v0.w * ws0 + v1.w * ws1;
        e += 2;
    }
    if (e < o1) {
        int p0 = __ldg(&epack[e]);
        int r0 = (unsigned)p0 >> 28;
        float4 v0 = __ldg((const float4*)(hb + ((size_t)(p0 & 0x0FFFFFFF) * 512 + (r0 << 7))));
        float ws0 = (r0 == 0) ? w0 : ((r0 == 1) ? w1 : w2);
        tx += v0.x * ws0; ty += v0.y * ws0; tz += v0.z * ws0; tw += v0.w * ws0;
    }

    if (do_relu) {
        tx = fmaxf(tx, 0.f); ty = fmaxf(ty, 0.f);
        tz = fmaxf(tz, 0.f); tw = fmaxf(tw, 0.f);
    }
    size_t idx = (size_t)node * HH + lane * 4;
    bf16 h0 = __float2bfloat16(tx), h1 = __float2bfloat16(ty);
    bf16 h2 = __float2bfloat16(tz), h3 = __float2bfloat16(tw);
    __nv_bfloat162 hh0(h0, h1), hh1(h2, h3);
    *(uint2*)&xh[idx] = make_uint2(*(uint32_t*)&hh0, *(uint32_t*)&hh1);
    __nv_bfloat162 ll0(__float2bfloat16(tx - __bfloat162float(h0)),
                       __float2bfloat16(ty - __bfloat162float(h1)));
    __nv_bfloat162 ll1(__float2bfloat16(tz - __bfloat162float(h2)),
                       __float2bfloat16(tw - __bfloat162float(h3)));
    *(uint2*)&xl[idx] = make_uint2(*(uint32_t*)&ll0, *(uint32_t*)&ll1);
}

// ---------------- edge apply: warp handles TWO edges (MLP=4) ----------------
__global__ __launch_bounds__(256)
void edge_apply(const float* __restrict__ UV,
                const int* __restrict__ src, const int* __restrict__ dst,
                const float* __restrict__ be1, const float* __restrict__ We2,
                const float* __restrict__ be2, float* __restrict__ out, int E) {
    __shared__ float sBe1[128];
    __shared__ float sW2[384];
    const int tid = threadIdx.x, lane = tid & 31;
    if (tid < 128) sBe1[tid] = be1[tid];
    for (int v = tid; v < 384; v += 256) sW2[v] = We2[v];
    __syncthreads();
    int gw = (blockIdx.x * 256 + tid) >> 5;
    int e0 = gw * 2;
    if (e0 >= E) return;
    int e1 = e0 + 1;
    bool has1 = e1 < E;
    int s0 = src[e0], d0 = dst[e0];
    int s1 = has1 ? src[e1] : s0;
    int d1 = has1 ? dst[e1] : d0;
    const int c = lane * 4;
    float4 u0 = __ldg((const float4*)(UV + (size_t)s0 * 256 + c));
    float4 v0 = __ldg((const float4*)(UV + (size_t)d0 * 256 + 128 + c));
    float4 u1 = __ldg((const float4*)(UV + (size_t)s1 * 256 + c));
    float4 v1 = __ldg((const float4*)(UV + (size_t)d1 * 256 + 128 + c));
    float be0 = sBe1[c + 0], be1_ = sBe1[c + 1], be2_ = sBe1[c + 2], be3 = sBe1[c + 3];
    float wa0 = sW2[(c + 0) * 3], wb0 = sW2[(c + 0) * 3 + 1], wc0 = sW2[(c + 0) * 3 + 2];
    float wa1 = sW2[(c + 1) * 3], wb1 = sW2[(c + 1) * 3 + 1], wc1 = sW2[(c + 1) * 3 + 2];
    float wa2 = sW2[(c + 2) * 3], wb2 = sW2[(c + 2) * 3 + 1], wc2 = sW2[(c + 2) * 3 + 2];
    float wa3 = sW2[(c + 3) * 3], wb3 = sW2[(c + 3) * 3 + 1], wc3 = sW2[(c + 3) * 3 + 2];

    float h;
    float a00 = 0.f, a01 = 0.f, a02 = 0.f;
    h = fmaxf(u0.x + v0.x + be0, 0.f); a00 += h * wa0; a01 += h * wb0; a02 += h * wc0;
    h = fmaxf(u0.y + v0.y + be1_, 0.f); a00 += h * wa1; a01 += h * wb1; a02 += h * wc1;
    h = fmaxf(u0.z + v0.z + be2_, 0.f); a00 += h * wa2; a01 += h * wb2; a02 += h * wc2;
    h = fmaxf(u0.w + v0.w + be3, 0.f); a00 += h * wa3; a01 += h * wb3; a02 += h * wc3;
    float a10 = 0.f, a11 = 0.f, a12 = 0.f;
    h = fmaxf(u1.x + v1.x + be0, 0.f); a10 += h * wa0; a11 += h * wb0; a12 += h * wc0;
    h = fmaxf(u1.y + v1.y + be1_, 0.f); a10 += h * wa1; a11 += h * wb1; a12 += h * wc1;
    h = fmaxf(u1.z + v1.z + be2_, 0.f); a10 += h * wa2; a11 += h * wb2; a12 += h * wc2;
    h = fmaxf(u1.w + v1.w + be3, 0.f); a10 += h * wa3; a11 += h * wb3; a12 += h * wc3;
#pragma unroll
    for (int o = 16; o; o >>= 1) {
        a00 += __shfl_xor_sync(0xFFFFFFFFu, a00, o);
        a01 += __shfl_xor_sync(0xFFFFFFFFu, a01, o);
        a02 += __shfl_xor_sync(0xFFFFFFFFu, a02, o);
        a10 += __shfl_xor_sync(0xFFFFFFFFu, a10, o);
        a11 += __shfl_xor_sync(0xFFFFFFFFu, a11, o);
        a12 += __shfl_xor_sync(0xFFFFFFFFu, a12, o);
    }
    if (lane == 0) {
        float g0 = __ldg(&be2[0]), g1 = __ldg(&be2[1]), g2 = __ldg(&be2[2]);
        out[(size_t)e0 * 3 + 0] = a00 + g0;
        out[(size_t)e0 * 3 + 1] = a01 + g1;
        out[(size_t)e0 * 3 + 2] = a02 + g2;
        if (has1) {
            out[(size_t)e1 * 3 + 0] = a10 + g0;
            out[(size_t)e1 * 3 + 1] = a11 + g1;
            out[(size_t)e1 * 3 + 2] = a12 + g2;
        }
    }
}

// ---------------- node head: 64 nodes/block; x3 reconstructed from xh+xl ----------------
__global__ __launch_bounds__(256)
void node_head_kernel(const bf16* __restrict__ xh, const bf16* __restrict__ xl,
                      const float* __restrict__ Wn1, const float* __restrict__ bn1,
                      const float* __restrict__ Wn2, const float* __restrict__ bn2,
                      float* __restrict__ out) {
    __shared__ float sW1[128 * 64];
    __shared__ float sb1[64];
    __shared__ float sW2[128];
    __shared__ float sx[4][128];
    __shared__ float sPart[8][2];
    const int tid = threadIdx.x;
    const int team = tid >> 6, t = tid & 63;      // 4 teams of 64
    const int wid = tid >> 5, lane = tid & 31;
    for (int i = tid; i < 128 * 64; i += 256) sW1[i] = Wn1[i];
    if (tid < 64) sb1[tid] = bn1[tid];
    if (tid < 128) sW2[tid] = Wn2[tid];
    float b20 = __ldg(&bn2[0]), b21 = __ldg(&bn2[1]);
    __syncthreads();
    const int base = blockIdx.x * 64;
#pragma unroll 1
    for (int it = 0; it < 16; it++) {
        int node = base + it * 4 + team;
        bool ok = node < NN;
        if (ok) {
            size_t off = (size_t)node * HH;
            sx[team][t]      = __bfloat162float(xh[off + t])      + __bfloat162float(xl[off + t]);
            sx[team][t + 64] = __bfloat162float(xh[off + t + 64]) + __bfloat162float(xl[off + t + 64]);
        }
        __syncthreads();
        float p0 = 0.f, p1 = 0.f;
        if (ok) {
            float acc = sb1[t];
#pragma unroll
            for (int k = 0; k < 128; k++) acc += sx[team][k] * sW1[k * 64 + t];
            float hgt = fmaxf(acc, 0.f);
            p0 = hgt * sW2[t * 2 + 0];
            p1 = hgt * sW2[t * 2 + 1];
        }
#pragma unroll
        for (int o = 16; o; o >>= 1) {
            p0 += __shfl_xor_sync(0xFFFFFFFFu, p0, o);
            p1 += __shfl_xor_sync(0xFFFFFFFFu, p1, o);
        }
        if (lane == 0) { sPart[wid][0] = p0; sPart[wid][1] = p1; }
        __syncthreads();
        if (ok && t == 0) {
            out[(size_t)node * 2 + 0] = sPart[team * 2][0] + sPart[team * 2 + 1][0] + b20;
            out[(size_t)node * 2 + 1] = sPart[team * 2][1] + sPart[team * 2 + 1][1] + b21;
        }
        __syncthreads();
    }
}

// ---------------- launch ----------------
extern "C" void kernel_launch(void* const* d_in, const int* in_sizes, int n_in,
                              void* d_out, int out_size) {
    const float* x       = (const float*)d_in[0];
    const int*   ei      = (const int*)d_in[1];
    const int*   et      = (const int*)d_in[2];
    const float* W_rel1  = (const float*)d_in[3];
    const float* W_root1 = (const float*)d_in[4];
    const float* b1      = (const float*)d_in[5];
    const float* W_rel2  = (const float*)d_in[6];
    const float* W_root2 = (const float*)d_in[7];
    const float* b2      = (const float*)d_in[8];
    const float* W_rel3  = (const float*)d_in[9];
    const float* W_root3 = (const float*)d_in[10];
    const float* b3      = (const float*)d_in[11];
    const float* We1     = (const float*)d_in[12];
    const float* be1     = (const float*)d_in[13];
    const float* We2     = (const float*)d_in[14];
    const float* be2     = (const float*)d_in[15];
    const float* Wn1     = (const float*)d_in[16];
    const float* bn1     = (const float*)d_in[17];
    const float* Wn2     = (const float*)d_in[18];
    const float* bn2     = (const float*)d_in[19];

    const int E = in_sizes[2];
    const int* src = ei;
    const int* dst = ei + E;

    bf16 *B1h, *B1l, *B2h, *B2l, *B3h, *B3l, *Weh, *Wel, *xh, *xl;
    float *hcomb;
    int *offs, *cur, *cnt3, *epack;
    cudaGetSymbolAddress((void**)&B1h, g_B1h);
    cudaGetSymbolAddress((void**)&B1l, g_B1l);
    cudaGetSymbolAddress((void**)&B2h, g_B2h);
    cudaGetSymbolAddress((void**)&B2l, g_B2l);
    cudaGetSymbolAddress((void**)&B3h, g_B3h);
    cudaGetSymbolAddress((void**)&B3l, g_B3l);
    cudaGetSymbolAddress((void**)&Weh, g_Weh);
    cudaGetSymbolAddress((void**)&Wel, g_Wel);
    cudaGetSymbolAddress((void**)&xh, g_xh);
    cudaGetSymbolAddress((void**)&xl, g_xl);
    cudaGetSymbolAddress((void**)&hcomb, g_hcomb);
    cudaGetSymbolAddress((void**)&offs, g_offs);
    cudaGetSymbolAddress((void**)&cur, g_cur);
    cudaGetSymbolAddress((void**)&cnt3, g_cnt3);
    cudaGetSymbolAddress((void**)&epack, g_epack);

    cudaFuncSetAttribute(gemm_mma, cudaFuncAttributeMaxDynamicSharedMemorySize, DYN_SMEM);

    float* out = (float*)d_out;
    float* edge_out = out;
    float* node_out = out + (size_t)E * 3;

    const int aggBlocks = (NN * 32 + 255) / 256;
    const int cntBlocks = (E + 255) / 256;
    const int edgeWarps = (E + 1) / 2;
    const int edgeBlocks = (edgeWarps * 32 + 255) / 256;
    dim3 gemmGrid(4, (NN + 127) / 128);
    dim3 uvGrid(2, (NN + 127) / 128);

    // ---- upfront (fused): weight packs + edge counts + input split ----
    cudaMemsetAsync(cur, 0, NN * sizeof(int));
    cudaMemsetAsync(cnt3, 0, NN * RR * sizeof(int));
    prep_kernel<<<PACK_BLOCKS + cntBlocks + SPLIT_BLOCKS, 256>>>(
        W_root1, W_rel1, W_root2, W_rel2, W_root3, W_rel3, We1,
        B1h, B1l, B2h, B2l, B3h, B3l, Weh, Wel,
        dst, et, cnt3, E, cntBlocks, x, xh, xl);
    scan_kernel<<<1, 1024>>>(cnt3, offs);
    fill_kernel<<<cntBlocks, 256>>>(src, dst, et, offs, cur, epack, E);

    // ---- layer 1 ----
    gemm_mma<<<gemmGrid, 256, DYN_SMEM>>>(xh, xl, B1h, B1l, hcomb, NN, INF, 512);
    agg_combine<<<aggBlocks, 256>>>(hcomb, offs, epack, cnt3, b1, xh, xl, 1);

    // ---- layer 2 ----
    gemm_mma<<<gemmGrid, 256, DYN_SMEM>>>(xh, xl, B2h, B2l, hcomb, NN, HH, 512);
    agg_combine<<<aggBlocks, 256>>>(hcomb, offs, epack, cnt3, b2, xh, xl, 1);

    // ---- layer 3 (no relu) ----
    gemm_mma<<<gemmGrid, 256, DYN_SMEM>>>(xh, xl, B3h, B3l, hcomb, NN, HH, 512);
    agg_combine<<<aggBlocks, 256>>>(hcomb, offs, epack, cnt3, b3, xh, xl, 0);

    // ---- edge head: UV GEMM, then per-edge apply (2 edges/warp) ----
    gemm_mma<<<uvGrid, 256, DYN_SMEM>>>(xh, xl, Weh, Wel, hcomb, NN, HH, 256);
    edge_apply<<<edgeBlocks, 256>>>(hcomb, src, dst, be1, We2, be2, edge_out, E);

    // ---- node head ----
    node_head_kernel<<<(NN + 63) / 64, 256>>>(xh, xl, Wn1, bn1, Wn2, bn2, node_out);
}

// round 16
// speedup vs baseline: 1.1153x; 1.0379x over previous
#include <cuda_runtime.h>
#include <cuda_bf16.h>
#include <cuda_fp16.h>
#include <cstdint>

// ---------------- problem constants ----------------
#define NN    50000
#define INF   768
#define HH    128
#define RR    3

typedef __nv_bfloat16 bf16;

// ---------------- scratch (device globals; no runtime alloc) ----------------
__device__ bf16   g_B1h[512 * INF];
__device__ bf16   g_B1l[512 * INF];
__device__ bf16   g_B2h[512 * HH];
__device__ bf16   g_B2l[512 * HH];
__device__ bf16   g_B3h[512 * HH];
__device__ bf16   g_B3l[512 * HH];
__device__ bf16   g_Weh[256 * 128];
__device__ bf16   g_Wel[256 * 128];
__device__ bf16   g_xh[(size_t)NN * INF];      // activation hi (bf16)
__device__ bf16   g_xl[(size_t)NN * INF];      // activation lo
__device__ float  g_hroot[(size_t)NN * 128];   // GEMM out, root cols (fp32)
__device__ __half g_hrel[(size_t)NN * 384];    // GEMM out, rel cols (fp16)
__device__ float  g_UV[(size_t)NN * 256];      // edge-head UV (fp32)
__device__ int    g_offs[NN + 1];
__device__ int    g_cur[NN];
__device__ int    g_cnt3[NN * RR];
__device__ int    g_epack[800000 + 64];        // CSR edge data: src | et<<28

// ================= helpers =================
__device__ __forceinline__ uint32_t smem_u32(const void* p) {
    uint32_t a;
    asm("{ .reg .u64 t; cvta.to.shared.u64 t, %1; cvt.u32.u64 %0, t; }" : "=r"(a) : "l"(p));
    return a;
}
// L2-only policy: staged tiles are consumed exactly once from smem.
__device__ __forceinline__ void cpasync16(uint32_t saddr, const void* g) {
    asm volatile("cp.async.cg.shared.global [%0], [%1], 16;" :: "r"(saddr), "l"(g));
}
#define CP_COMMIT() asm volatile("cp.async.commit_group;" ::: "memory")
#define CP_WAIT1()  asm volatile("cp.async.wait_group 1;" ::: "memory")
#define CP_WAIT0()  asm volatile("cp.async.wait_group 0;" ::: "memory")

__device__ __forceinline__ void ldsm4(uint32_t (&r)[4], uint32_t addr) {
    asm volatile("ldmatrix.sync.aligned.m8n8.x4.shared.b16 {%0,%1,%2,%3}, [%4];"
                 : "=r"(r[0]), "=r"(r[1]), "=r"(r[2]), "=r"(r[3]) : "r"(addr));
}
__device__ __forceinline__ void mma_bf16(float (&d)[4], const uint32_t (&a)[4],
                                         uint32_t b0, uint32_t b1) {
    asm volatile("mma.sync.aligned.m16n8k16.row.col.f32.bf16.bf16.f32 "
                 "{%0,%1,%2,%3}, {%4,%5,%6,%7}, {%8,%9}, {%0,%1,%2,%3};"
                 : "+f"(d[0]), "+f"(d[1]), "+f"(d[2]), "+f"(d[3])
                 : "r"(a[0]), "r"(a[1]), "r"(a[2]), "r"(a[3]), "r"(b0), "r"(b1));
}

// smem tile: 128 rows x 4 chunks of 16B. XOR swizzle.
__device__ __forceinline__ uint32_t swz(int row, int chunk) {
    return (uint32_t)(((row << 2) + (chunk ^ ((row >> 1) & 3))) << 4);
}
#define TILE_B  8192
#define STAGE_B (4 * TILE_B)
#define NSTAGE  3
#define DYN_SMEM (NSTAGE * STAGE_B)    // 96 KB

// ---------------- stage loader ----------------
__device__ __forceinline__ void load_stage_dense(
    uint32_t sb, const bf16* __restrict__ Ah, const bf16* __restrict__ Al,
    const bf16* __restrict__ Bh, const bf16* __restrict__ Bl,
    int K, int bm, int n0, int k0, int M, int tid) {
#pragma unroll
    for (int i = 0; i < 2; i++) {
        int cid = tid * 2 + i;
        int row = cid >> 2, ch = cid & 3;
        int gm = bm + row; if (gm >= M) gm = M - 1;
        size_t ga = (size_t)gm * K + k0 + ch * 8;
        uint32_t so = swz(row, ch);
        cpasync16(sb + so, Ah + ga);
        cpasync16(sb + TILE_B + so, Al + ga);
        size_t gb = (size_t)(n0 + row) * K + k0 + ch * 8;
        cpasync16(sb + 2 * TILE_B + so, Bh + gb);
        cpasync16(sb + 3 * TILE_B + so, Bl + gb);
    }
}

// ---------------- warp-tile compute (64x32, bf16x3) ----------------
__device__ __forceinline__ void compute_stage(float (&acc)[4][4][4], uint32_t sb,
                                              int m0w, int n0w, int lane) {
#pragma unroll
    for (int kf = 0; kf < 2; kf++) {
        uint32_t ah[4][4], al[4][4], bh[2][4], bl[2][4];
        const int arow = lane & 15;
        const int ach = kf * 2 + (lane >> 4);
        const int brow = n0w + ((lane >> 4) << 3) + (lane & 7);
        const int bch = kf * 2 + ((lane >> 3) & 1);
#pragma unroll
        for (int mf = 0; mf < 4; mf++)
            ldsm4(ah[mf], sb + swz(m0w + mf * 16 + arow, ach));
#pragma unroll
        for (int p = 0; p < 2; p++)
            ldsm4(bh[p], sb + 2 * TILE_B + swz(brow + p * 16, bch));
#pragma unroll
        for (int mf = 0; mf < 4; mf++)
#pragma unroll
            for (int nf = 0; nf < 4; nf++)
                mma_bf16(acc[mf][nf], ah[mf], bh[nf >> 1][(nf & 1) * 2], bh[nf >> 1][(nf & 1) * 2 + 1]);
#pragma unroll
        for (int p = 0; p < 2; p++)
            ldsm4(bl[p], sb + 3 * TILE_B + swz(brow + p * 16, bch));
#pragma unroll
        for (int mf = 0; mf < 4; mf++)
#pragma unroll
            for (int nf = 0; nf < 4; nf++)
                mma_bf16(acc[mf][nf], ah[mf], bl[nf >> 1][(nf & 1) * 2], bl[nf >> 1][(nf & 1) * 2 + 1]);
#pragma unroll
        for (int mf = 0; mf < 4; mf++)
            ldsm4(al[mf], sb + TILE_B + swz(m0w + mf * 16 + arow, ach));
#pragma unroll
        for (int mf = 0; mf < 4; mf++)
#pragma unroll
            for (int nf = 0; nf < 4; nf++)
                mma_bf16(acc[mf][nf], al[mf], bh[nf >> 1][(nf & 1) * 2], bh[nf >> 1][(nf & 1) * 2 + 1]);
    }
}

// ---------------- GEMM: 3-stage cp.async pipeline; fp32 root / fp16 rel output ----------------
__global__ __launch_bounds__(256)
void gemm_mma(const bf16* __restrict__ Ah, const bf16* __restrict__ Al,
              const bf16* __restrict__ Bh, const bf16* __restrict__ Bl,
              float* __restrict__ Cf, __half* __restrict__ Ch,
              int M, int K, int ldcF, int relHalf) {
    extern __shared__ char dsm[];
    const uint32_t sb = smem_u32(dsm);
    const int tid = threadIdx.x, lane = tid & 31, wid = tid >> 5;
    const int bm = blockIdx.y * 128, n0 = blockIdx.x * 128;
    const int m0w = (wid >> 2) * 64, n0w = (wid & 3) * 32;
    float acc[4][4][4];
#pragma unroll
    for (int a = 0; a < 4; a++)
#pragma unroll
        for (int b = 0; b < 4; b++)
#pragma unroll
            for (int c = 0; c < 4; c++) acc[a][b][c] = 0.f;

    const int niter = K / 32;   // always >= 2 here
    load_stage_dense(sb, Ah, Al, Bh, Bl, K, bm, n0, 0, M, tid);
    CP_COMMIT();
    load_stage_dense(sb + STAGE_B, Ah, Al, Bh, Bl, K, bm, n0, 32, M, tid);
    CP_COMMIT();

    int buf = 0;
    for (int it = 0; it < niter; it++) {
        if (it + 1 < niter) CP_WAIT1(); else CP_WAIT0();
        __syncthreads();
        if (it + 2 < niter) {
            int nb = buf + 2; if (nb >= NSTAGE) nb -= NSTAGE;
            load_stage_dense(sb + nb * STAGE_B, Ah, Al, Bh, Bl, K, bm, n0, (it + 2) * 32, M, tid);
            CP_COMMIT();
        }
        compute_stage(acc, sb + buf * STAGE_B, m0w, n0w, lane);
        if (++buf == NSTAGE) buf = 0;
    }

    const bool halfPath = relHalf && (n0 >= 128);
#pragma unroll
    for (int mf = 0; mf < 4; mf++) {
#pragma unroll
        for (int nf = 0; nf < 4; nf++) {
            int col = n0 + n0w + nf * 8 + (lane & 3) * 2;
            int r0 = bm + m0w + mf * 16 + (lane >> 2);
            int r1 = r0 + 8;
            if (halfPath) {
                int cr = col - 128;
                if (r0 < M)
                    *(__half2*)&Ch[(size_t)r0 * 384 + cr] =
                        __floats2half2_rn(acc[mf][nf][0], acc[mf][nf][1]);
                if (r1 < M)
                    *(__half2*)&Ch[(size_t)r1 * 384 + cr] =
                        __floats2half2_rn(acc[mf][nf][2], acc[mf][nf][3]);
            } else {
                if (r0 < M)
                    *(float2*)&Cf[(size_t)r0 * ldcF + col] = make_float2(acc[mf][nf][0], acc[mf][nf][1]);
                if (r1 < M)
                    *(float2*)&Cf[(size_t)r1 * ldcF + col] = make_float2(acc[mf][nf][2], acc[mf][nf][3]);
            }
        }
    }
}

// ---------------- prep: pack_all + cnt + split fused via block-range dispatch ----------------
__device__ __forceinline__ void pack_one(float v, bf16* __restrict__ Bh,
                                         bf16* __restrict__ Bl, int idx) {
    bf16 h = __float2bfloat16(v);
    Bh[idx] = h;
    Bl[idx] = __float2bfloat16(v - __bfloat162float(h));
}
__device__ __forceinline__ float layer_w(const float* __restrict__ W_root,
                                         const float* __restrict__ W_rel,
                                         int idx, int K) {
    int n = idx / K, k = idx % K;
    if (n < HH) return W_root[k * HH + n];
    return W_rel[((size_t)((n >> 7) - 1) * K + k) * HH + (n & 127)];
}
#define P1 (512 * INF)
#define P2 (512 * HH)
#define PACK_TOTAL  (P1 + 2 * P2 + 256 * 128)
#define PACK_BLOCKS ((PACK_TOTAL + 255) / 256)
#define SPLIT_N4    (NN * INF / 4)
#define SPLIT_BLOCKS ((SPLIT_N4 + 255) / 256)

__global__ __launch_bounds__(256)
void prep_kernel(const float* __restrict__ Wr1, const float* __restrict__ Wrel1,
                 const float* __restrict__ Wr2, const float* __restrict__ Wrel2,
                 const float* __restrict__ Wr3, const float* __restrict__ Wrel3,
                 const float* __restrict__ We1,
                 bf16* B1h, bf16* B1l, bf16* B2h, bf16* B2l,
                 bf16* B3h, bf16* B3l, bf16* Weh, bf16* Wel,
                 const int* __restrict__ dst, const int* __restrict__ et,
                 int* __restrict__ cnt3, int E, int cntBlocks,
                 const float* __restrict__ x, bf16* __restrict__ xh, bf16* __restrict__ xl) {
    int blk = blockIdx.x;
    if (blk < PACK_BLOCKS) {
        int idx = blk * 256 + threadIdx.x;
        if (idx < P1) {
            pack_one(layer_w(Wr1, Wrel1, idx, INF), B1h, B1l, idx);
        } else if (idx < P1 + P2) {
            int i = idx - P1;
            pack_one(layer_w(Wr2, Wrel2, i, HH), B2h, B2l, i);
        } else if (idx < P1 + 2 * P2) {
            int i = idx - P1 - P2;
            pack_one(layer_w(Wr3, Wrel3, i, HH), B3h, B3l, i);
        } else if (idx < PACK_TOTAL) {
            int i = idx - P1 - 2 * P2;
            int n = i / 128, k = i % 128;
            float v = (n < 128) ? We1[k * 128 + n] : We1[(128 + k) * 128 + (n - 128)];
            pack_one(v, Weh, Wel, i);
        }
        return;
    }
    blk -= PACK_BLOCKS;
    if (blk < cntBlocks) {
        int i = blk * 256 + threadIdx.x;
        if (i < E) atomicAdd(&cnt3[dst[i] * RR + et[i]], 1);
        return;
    }
    blk -= cntBlocks;
    {
        int i = blk * 256 + threadIdx.x;
        if (i >= SPLIT_N4) return;
        float4 v = ((const float4*)x)[i];
        bf16 h0 = __float2bfloat16(v.x), h1 = __float2bfloat16(v.y);
        bf16 h2 = __float2bfloat16(v.z), h3 = __float2bfloat16(v.w);
        ((__nv_bfloat162*)xh)[i * 2]     = __nv_bfloat162(h0, h1);
        ((__nv_bfloat162*)xh)[i * 2 + 1] = __nv_bfloat162(h2, h3);
        ((__nv_bfloat162*)xl)[i * 2]     = __nv_bfloat162(__float2bfloat16(v.x - __bfloat162float(h0)),
                                                          __float2bfloat16(v.y - __bfloat162float(h1)));
        ((__nv_bfloat162*)xl)[i * 2 + 1] = __nv_bfloat162(__float2bfloat16(v.z - __bfloat162float(h2)),
                                                          __float2bfloat16(v.w - __bfloat162float(h3)));
    }
}

// ---------------- scan over cnt3 triplets -> offs ----------------
__global__ void scan_kernel(const int* __restrict__ cnt3, int* __restrict__ offs) {
    __shared__ int warp_sums[32];
    __shared__ int s_carry;
    const int t = threadIdx.x;          // 1024 threads, single block
    const int lane = t & 31, w = t >> 5;
    if (t == 0) { s_carry = 0; offs[0] = 0; }
    __syncthreads();
    for (int base = 0; base < NN; base += 1024) {
        int i = base + t;
        int v = 0;
        if (i < NN)
            v = cnt3[i * RR + 0] + cnt3[i * RR + 1] + cnt3[i * RR + 2];
        int x = v;
#pragma unroll
        for (int o = 1; o < 32; o <<= 1) {
            int y = __shfl_up_sync(0xFFFFFFFFu, x, o);
            if (lane >= o) x += y;
        }
        if (lane == 31) warp_sums[w] = x;
        __syncthreads();
        if (w == 0) {
            int s = warp_sums[lane];
#pragma unroll
            for (int o = 1; o < 32; o <<= 1) {
                int y = __shfl_up_sync(0xFFFFFFFFu, s, o);
                if (lane >= o) s += y;
            }
            warp_sums[lane] = s;
        }
        __syncthreads();
        int incl = x + (w > 0 ? warp_sums[w - 1] : 0) + s_carry;
        if (i < NN) offs[i + 1] = incl;
        __syncthreads();
        if (t == 1023) s_carry = incl;
        __syncthreads();
    }
}

__global__ void fill_kernel(const int* __restrict__ src, const int* __restrict__ dst,
                            const int* __restrict__ et, const int* __restrict__ offs,
                            int* __restrict__ cur, int* __restrict__ epack, int E) {
    int i = blockIdx.x * blockDim.x + threadIdx.x;
    if (i >= E) return;
    int d = dst[i];
    int p = atomicAdd(&cur[d], 1);
    epack[offs[d] + p] = src[i] | (et[i] << 28);
}

// ---------------- fused aggregation: warp/node, fp16 rel gathers ----------------
__device__ __forceinline__ void half8_to_f4(uint2 q, float& x, float& y, float& z, float& w) {
    float2 a = __half22float2(*(__half2*)&q.x);
    float2 b = __half22float2(*(__half2*)&q.y);
    x = a.x; y = a.y; z = b.x; w = b.y;
}

__global__ __launch_bounds__(256)
void agg_combine(const float* __restrict__ hroot, const __half* __restrict__ hrel,
                 const int* __restrict__ offs, const int* __restrict__ epack,
                 const int* __restrict__ cnt3, const float* __restrict__ b,
                 bf16* __restrict__ xh, bf16* __restrict__ xl, int do_relu) {
    int node = (blockIdx.x * blockDim.x + threadIdx.x) >> 5;
    int lane = threadIdx.x & 31;
    if (node >= NN) return;
    const int o0 = offs[node], o1 = offs[node + 1];
    const float w0 = 1.f / (float)max(__ldg(&cnt3[node * RR + 0]), 1);
    const float w1 = 1.f / (float)max(__ldg(&cnt3[node * RR + 1]), 1);
    const float w2 = 1.f / (float)max(__ldg(&cnt3[node * RR + 2]), 1);

    float4 root = *(const float4*)&hroot[(size_t)node * 128 + lane * 4];
    float4 bb = *(const float4*)&b[lane * 4];
    float tx = root.x + bb.x, ty = root.y + bb.y;
    float tz = root.z + bb.z, tw = root.w + bb.w;

    const __half* __restrict__ hb = hrel + lane * 4;
    int e = o0;
    for (; e + 4 <= o1; e += 4) {
        int p0 = __ldg(&epack[e + 0]);
        int p1 = __ldg(&epack[e + 1]);
        int p2 = __ldg(&epack[e + 2]);
        int p3 = __ldg(&epack[e + 3]);
        int r0 = (unsigned)p0 >> 28, r1 = (unsigned)p1 >> 28;
        int r2 = (unsigned)p2 >> 28, r3 = (unsigned)p3 >> 28;
        uint2 q0 = __ldg((const uint2*)(hb + ((size_t)(p0 & 0x0FFFFFFF) * 384 + (r0 << 7))));
        uint2 q1 = __ldg((const uint2*)(hb + ((size_t)(p1 & 0x0FFFFFFF) * 384 + (r1 << 7))));
        uint2 q2 = __ldg((const uint2*)(hb + ((size_t)(p2 & 0x0FFFFFFF) * 384 + (r2 << 7))));
        uint2 q3 = __ldg((const uint2*)(hb + ((size_t)(p3 & 0x0FFFFFFF) * 384 + (r3 << 7))));
        float ws0 = (r0 == 0) ? w0 : ((r0 == 1) ? w1 : w2);
        float ws1 = (r1 == 0) ? w0 : ((r1 == 1) ? w1 : w2);
        float ws2 = (r2 == 0) ? w0 : ((r2 == 1) ? w1 : w2);
        float ws3 = (r3 == 0) ? w0 : ((r3 == 1) ? w1 : w2);
        float vx, vy, vz, vw;
        half8_to_f4(q0, vx, vy, vz, vw);
        tx += vx * ws0; ty += vy * ws0; tz += vz * ws0; tw += vw * ws0;
        half8_to_f4(q1, vx, vy, vz, vw);
        tx += vx * ws1; ty += vy * ws1; tz += vz * ws1; tw += vw * ws1;
        half8_to_f4(q2, vx, vy, vz, vw);
        tx += vx * ws2; ty += vy * ws2; tz += vz * ws2; tw += vw * ws2;
        half8_to_f4(q3, vx, vy, vz, vw);
        tx += vx * ws3; ty += vy * ws3; tz += vz * ws3; tw += vw * ws3;
    }
    if (e + 2 <= o1) {
        int p0 = __ldg(&epack[e + 0]);
        int p1 = __ldg(&epack[e + 1]);
        int r0 = (unsigned)p0 >> 28, r1 = (unsigned)p1 >> 28;
        uint2 q0 = __ldg((const uint2*)(hb + ((size_t)(p0 & 0x0FFFFFFF) * 384 + (r0 << 7))));
        uint2 q1 = __ldg((const uint2*)(hb + ((size_t)(p1 & 0x0FFFFFFF) * 384 + (r1 << 7))));
        float ws0 = (r0 == 0) ? w0 : ((r0 == 1) ? w1 : w2);
        float ws1 = (r1 == 0) ? w0 : ((r1 == 1) ? w1 : w2);
        float vx, vy, vz, vw;
        half8_to_f4(q0, vx, vy, vz, vw);
        tx += vx * ws0; ty += vy * ws0; tz += vz * ws0; tw += vw * ws0;
        half8_to_f4(q1, vx, vy, vz, vw);
        tx += vx * ws1; ty += vy * ws1; tz += vz * ws1; tw += vw * ws1;
        e += 2;
    }
    if (e < o1) {
        int p0 = __ldg(&epack[e]);
        int r0 = (unsigned)p0 >> 28;
        uint2 q0 = __ldg((const uint2*)(hb + ((size_t)(p0 & 0x0FFFFFFF) * 384 + (r0 << 7))));
        float ws0 = (r0 == 0) ? w0 : ((r0 == 1) ? w1 : w2);
        float vx, vy, vz, vw;
        half8_to_f4(q0, vx, vy, vz, vw);
        tx += vx * ws0; ty += vy * ws0; tz += vz * ws0; tw += vw * ws0;
    }

    if (do_relu) {
        tx = fmaxf(tx, 0.f); ty = fmaxf(ty, 0.f);
        tz = fmaxf(tz, 0.f); tw = fmaxf(tw, 0.f);
    }
    size_t idx = (size_t)node * HH + lane * 4;
    bf16 h0 = __float2bfloat16(tx), h1 = __float2bfloat16(ty);
    bf16 h2 = __float2bfloat16(tz), h3 = __float2bfloat16(tw);
    __nv_bfloat162 hh0(h0, h1), hh1(h2, h3);
    *(uint2*)&xh[idx] = make_uint2(*(uint32_t*)&hh0, *(uint32_t*)&hh1);
    __nv_bfloat162 ll0(__float2bfloat16(tx - __bfloat162float(h0)),
                       __float2bfloat16(ty - __bfloat162float(h1)));
    __nv_bfloat162 ll1(__float2bfloat16(tz - __bfloat162float(h2)),
                       __float2bfloat16(tw - __bfloat162float(h3)));
    *(uint2*)&xl[idx] = make_uint2(*(uint32_t*)&ll0, *(uint32_t*)&ll1);
}

// ---------------- edge apply: warp handles TWO edges (MLP=4) ----------------
__global__ __launch_bounds__(256)
void edge_apply(const float* __restrict__ UV,
                const int* __restrict__ src, const int* __restrict__ dst,
                const float* __restrict__ be1, const float* __restrict__ We2,
                const float* __restrict__ be2, float* __restrict__ out, int E) {
    __shared__ float sBe1[128];
    __shared__ float sW2[384];
    const int tid = threadIdx.x, lane = tid & 31;
    if (tid < 128) sBe1[tid] = be1[tid];
    for (int v = tid; v < 384; v += 256) sW2[v] = We2[v];
    __syncthreads();
    int gw = (blockIdx.x * 256 + tid) >> 5;
    int e0 = gw * 2;
    if (e0 >= E) return;
    int e1 = e0 + 1;
    bool has1 = e1 < E;
    int s0 = src[e0], d0 = dst[e0];
    int s1 = has1 ? src[e1] : s0;
    int d1 = has1 ? dst[e1] : d0;
    const int c = lane * 4;
    float4 u0 = __ldg((const float4*)(UV + (size_t)s0 * 256 + c));
    float4 v0 = __ldg((const float4*)(UV + (size_t)d0 * 256 + 128 + c));
    float4 u1 = __ldg((const float4*)(UV + (size_t)s1 * 256 + c));
    float4 v1 = __ldg((const float4*)(UV + (size_t)d1 * 256 + 128 + c));
    float be0 = sBe1[c + 0], be1_ = sBe1[c + 1], be2_ = sBe1[c + 2], be3 = sBe1[c + 3];
    float wa0 = sW2[(c + 0) * 3], wb0 = sW2[(c + 0) * 3 + 1], wc0 = sW2[(c + 0) * 3 + 2];
    float wa1 = sW2[(c + 1) * 3], wb1 = sW2[(c + 1) * 3 + 1], wc1 = sW2[(c + 1) * 3 + 2];
    float wa2 = sW2[(c + 2) * 3], wb2 = sW2[(c + 2) * 3 + 1], wc2 = sW2[(c + 2) * 3 + 2];
    float wa3 = sW2[(c + 3) * 3], wb3 = sW2[(c + 3) * 3 + 1], wc3 = sW2[(c + 3) * 3 + 2];

    float h;
    float a00 = 0.f, a01 = 0.f, a02 = 0.f;
    h = fmaxf(u0.x + v0.x + be0, 0.f); a00 += h * wa0; a01 += h * wb0; a02 += h * wc0;
    h = fmaxf(u0.y + v0.y + be1_, 0.f); a00 += h * wa1; a01 += h * wb1; a02 += h * wc1;
    h = fmaxf(u0.z + v0.z + be2_, 0.f); a00 += h * wa2; a01 += h * wb2; a02 += h * wc2;
    h = fmaxf(u0.w + v0.w + be3, 0.f); a00 += h * wa3; a01 += h * wb3; a02 += h * wc3;
    float a10 = 0.f, a11 = 0.f, a12 = 0.f;
    h = fmaxf(u1.x + v1.x + be0, 0.f); a10 += h * wa0; a11 += h * wb0; a12 += h * wc0;
    h = fmaxf(u1.y + v1.y + be1_, 0.f); a10 += h * wa1; a11 += h * wb1; a12 += h * wc1;
    h = fmaxf(u1.z + v1.z + be2_, 0.f); a10 += h * wa2; a11 += h * wb2; a12 += h * wc2;
    h = fmaxf(u1.w + v1.w + be3, 0.f); a10 += h * wa3; a11 += h * wb3; a12 += h * wc3;
#pragma unroll
    for (int o = 16; o; o >>= 1) {
        a00 += __shfl_xor_sync(0xFFFFFFFFu, a00, o);
        a01 += __shfl_xor_sync(0xFFFFFFFFu, a01, o);
        a02 += __shfl_xor_sync(0xFFFFFFFFu, a02, o);
        a10 += __shfl_xor_sync(0xFFFFFFFFu, a10, o);
        a11 += __shfl_xor_sync(0xFFFFFFFFu, a11, o);
        a12 += __shfl_xor_sync(0xFFFFFFFFu, a12, o);
    }
    if (lane == 0) {
        float g0 = __ldg(&be2[0]), g1 = __ldg(&be2[1]), g2 = __ldg(&be2[2]);
        out[(size_t)e0 * 3 + 0] = a00 + g0;
        out[(size_t)e0 * 3 + 1] = a01 + g1;
        out[(size_t)e0 * 3 + 2] = a02 + g2;
        if (has1) {
            out[(size_t)e1 * 3 + 0] = a10 + g0;
            out[(size_t)e1 * 3 + 1] = a11 + g1;
            out[(size_t)e1 * 3 + 2] = a12 + g2;
        }
    }
}

// ---------------- node head: 64 nodes/block; x3 reconstructed from xh+xl ----------------
__global__ __launch_bounds__(256)
void node_head_kernel(const bf16* __restrict__ xh, const bf16* __restrict__ xl,
                      const float* __restrict__ Wn1, const float* __restrict__ bn1,
                      const float* __restrict__ Wn2, const float* __restrict__ bn2,
                      float* __restrict__ out) {
    __shared__ float sW1[128 * 64];
    __shared__ float sb1[64];
    __shared__ float sW2[128];
    __shared__ float sx[4][128];
    __shared__ float sPart[8][2];
    const int tid = threadIdx.x;
    const int team = tid >> 6, t = tid & 63;      // 4 teams of 64
    const int wid = tid >> 5, lane = tid & 31;
    for (int i = tid; i < 128 * 64; i += 256) sW1[i] = Wn1[i];
    if (tid < 64) sb1[tid] = bn1[tid];
    if (tid < 128) sW2[tid] = Wn2[tid];
    float b20 = __ldg(&bn2[0]), b21 = __ldg(&bn2[1]);
    __syncthreads();
    const int base = blockIdx.x * 64;
#pragma unroll 1
    for (int it = 0; it < 16; it++) {
        int node = base + it * 4 + team;
        bool ok = node < NN;
        if (ok) {
            size_t off = (size_t)node * HH;
            sx[team][t]      = __bfloat162float(xh[off + t])      + __bfloat162float(xl[off + t]);
            sx[team][t + 64] = __bfloat162float(xh[off + t + 64]) + __bfloat162float(xl[off + t + 64]);
        }
        __syncthreads();
        float p0 = 0.f, p1 = 0.f;
        if (ok) {
            float acc = sb1[t];
#pragma unroll
            for (int k = 0; k < 128; k++) acc += sx[team][k] * sW1[k * 64 + t];
            float hgt = fmaxf(acc, 0.f);
            p0 = hgt * sW2[t * 2 + 0];
            p1 = hgt * sW2[t * 2 + 1];
        }
#pragma unroll
        for (int o = 16; o; o >>= 1) {
            p0 += __shfl_xor_sync(0xFFFFFFFFu, p0, o);
            p1 += __shfl_xor_sync(0xFFFFFFFFu, p1, o);
        }
        if (lane == 0) { sPart[wid][0] = p0; sPart[wid][1] = p1; }
        __syncthreads();
        if (ok && t == 0) {
            out[(size_t)node * 2 + 0] = sPart[team * 2][0] + sPart[team * 2 + 1][0] + b20;
            out[(size_t)node * 2 + 1] = sPart[team * 2][1] + sPart[team * 2 + 1][1] + b21;
        }
        __syncthreads();
    }
}

// ---------------- launch ----------------
extern "C" void kernel_launch(void* const* d_in, const int* in_sizes, int n_in,
                              void* d_out, int out_size) {
    const float* x       = (const float*)d_in[0];
    const int*   ei      = (const int*)d_in[1];
    const int*   et      = (const int*)d_in[2];
    const float* W_rel1  = (const float*)d_in[3];
    const float* W_root1 = (const float*)d_in[4];
    const float* b1      = (const float*)d_in[5];
    const float* W_rel2  = (const float*)d_in[6];
    const float* W_root2 = (const float*)d_in[7];
    const float* b2      = (const float*)d_in[8];
    const float* W_rel3  = (const float*)d_in[9];
    const float* W_root3 = (const float*)d_in[10];
    const float* b3      = (const float*)d_in[11];
    const float* We1     = (const float*)d_in[12];
    const float* be1     = (const float*)d_in[13];
    const float* We2     = (const float*)d_in[14];
    const float* be2     = (const float*)d_in[15];
    const float* Wn1     = (const float*)d_in[16];
    const float* bn1     = (const float*)d_in[17];
    const float* Wn2     = (const float*)d_in[18];
    const float* bn2     = (const float*)d_in[19];

    const int E = in_sizes[2];
    const int* src = ei;
    const int* dst = ei + E;

    bf16 *B1h, *B1l, *B2h, *B2l, *B3h, *B3l, *Weh, *Wel, *xh, *xl;
    float *hroot, *UV;
    __half *hrel;
    int *offs, *cur, *cnt3, *epack;
    cudaGetSymbolAddress((void**)&B1h, g_B1h);
    cudaGetSymbolAddress((void**)&B1l, g_B1l);
    cudaGetSymbolAddress((void**)&B2h, g_B2h);
    cudaGetSymbolAddress((void**)&B2l, g_B2l);
    cudaGetSymbolAddress((void**)&B3h, g_B3h);
    cudaGetSymbolAddress((void**)&B3l, g_B3l);
    cudaGetSymbolAddress((void**)&Weh, g_Weh);
    cudaGetSymbolAddress((void**)&Wel, g_Wel);
    cudaGetSymbolAddress((void**)&xh, g_xh);
    cudaGetSymbolAddress((void**)&xl, g_xl);
    cudaGetSymbolAddress((void**)&hroot, g_hroot);
    cudaGetSymbolAddress((void**)&hrel, g_hrel);
    cudaGetSymbolAddress((void**)&UV, g_UV);
    cudaGetSymbolAddress((void**)&offs, g_offs);
    cudaGetSymbolAddress((void**)&cur, g_cur);
    cudaGetSymbolAddress((void**)&cnt3, g_cnt3);
    cudaGetSymbolAddress((void**)&epack, g_epack);

    cudaFuncSetAttribute(gemm_mma, cudaFuncAttributeMaxDynamicSharedMemorySize, DYN_SMEM);

    float* out = (float*)d_out;
    float* edge_out = out;
    float* node_out = out + (size_t)E * 3;

    const int aggBlocks = (NN * 32 + 255) / 256;
    const int cntBlocks = (E + 255) / 256;
    const int edgeWarps = (E + 1) / 2;
    const int edgeBlocks = (edgeWarps * 32 + 255) / 256;
    dim3 gemmGrid(4, (NN + 127) / 128);
    dim3 uvGrid(2, (NN + 127) / 128);

    // ---- upfront (fused): weight packs + edge counts + input split ----
    cudaMemsetAsync(cur, 0, NN * sizeof(int));
    cudaMemsetAsync(cnt3, 0, NN * RR * sizeof(int));
    prep_kernel<<<PACK_BLOCKS + cntBlocks + SPLIT_BLOCKS, 256>>>(
        W_root1, W_rel1, W_root2, W_rel2, W_root3, W_rel3, We1,
        B1h, B1l, B2h, B2l, B3h, B3l, Weh, Wel,
        dst, et, cnt3, E, cntBlocks, x, xh, xl);
    scan_kernel<<<1, 1024>>>(cnt3, offs);
    fill_kernel<<<cntBlocks, 256>>>(src, dst, et, offs, cur, epack, E);

    // ---- layer 1 ----
    gemm_mma<<<gemmGrid, 256, DYN_SMEM>>>(xh, xl, B1h, B1l, hroot, hrel, NN, INF, 128, 1);
    agg_combine<<<aggBlocks, 256>>>(hroot, hrel, offs, epack, cnt3, b1, xh, xl, 1);

    // ---- layer 2 ----
    gemm_mma<<<gemmGrid, 256, DYN_SMEM>>>(xh, xl, B2h, B2l, hroot, hrel, NN, HH, 128, 1);
    agg_combine<<<aggBlocks, 256>>>(hroot, hrel, offs, epack, cnt3, b2, xh, xl, 1);

    // ---- layer 3 (no relu) ----
    gemm_mma<<<gemmGrid, 256, DYN_SMEM>>>(xh, xl, B3h, B3l, hroot, hrel, NN, HH, 128, 1);
    agg_combine<<<aggBlocks, 256>>>(hroot, hrel, offs, epack, cnt3, b3, xh, xl, 0);

    // ---- edge head: UV GEMM (fp32), then per-edge apply (2 edges/warp) ----
    gemm_mma<<<uvGrid, 256, DYN_SMEM>>>(xh, xl, Weh, Wel, UV, hrel, NN, HH, 256, 0);
    edge_apply<<<edgeBlocks, 256>>>(UV, src, dst, be1, We2, be2, edge_out, E);

    // ---- node head ----
    node_head_kernel<<<(NN + 63) / 64, 256>>>(xh, xl, Wn1, bn1, Wn2, bn2, node_out);
}

// round 17
// speedup vs baseline: 1.1156x; 1.0003x over previous
#include <cuda_runtime.h>
#include <cuda_bf16.h>
#include <cuda_fp16.h>
#include <cstdint>

// ---------------- problem constants ----------------
#define NN    50000
#define INF   768
#define HH    128
#define RR    3

typedef __nv_bfloat16 bf16;

// ---------------- scratch (device globals; no runtime alloc) ----------------
__device__ bf16   g_B1h[512 * INF];
__device__ bf16   g_B1l[512 * INF];
__device__ bf16   g_B2h[512 * HH];
__device__ bf16   g_B2l[512 * HH];
__device__ bf16   g_B3h[512 * HH];
__device__ bf16   g_B3l[512 * HH];
__device__ bf16   g_Weh[256 * 128];
__device__ bf16   g_Wel[256 * 128];
__device__ bf16   g_xh[(size_t)NN * INF];      // activation hi (bf16)
__device__ bf16   g_xl[(size_t)NN * INF];      // activation lo
__device__ float  g_hroot[(size_t)NN * 128];   // GEMM out, root cols (fp32)
__device__ __half g_hrel[(size_t)NN * 384];    // GEMM out, rel cols (fp16)
__device__ float  g_UV[(size_t)NN * 256];      // edge-head UV (fp32)
__device__ int    g_offs[NN + 1];
__device__ int    g_cur[NN];
__device__ int    g_cnt3[NN * RR];
__device__ int    g_epack[800000 + 64];        // CSR edge data: src | et<<28

// ================= helpers =================
__device__ __forceinline__ uint32_t smem_u32(const void* p) {
    uint32_t a;
    asm("{ .reg .u64 t; cvta.to.shared.u64 t, %1; cvt.u32.u64 %0, t; }" : "=r"(a) : "l"(p));
    return a;
}
// L2-only policy: staged tiles are consumed exactly once from smem.
__device__ __forceinline__ void cpasync16(uint32_t saddr, const void* g) {
    asm volatile("cp.async.cg.shared.global [%0], [%1], 16;" :: "r"(saddr), "l"(g));
}
#define CP_COMMIT() asm volatile("cp.async.commit_group;" ::: "memory")
#define CP_WAIT1()  asm volatile("cp.async.wait_group 1;" ::: "memory")
#define CP_WAIT0()  asm volatile("cp.async.wait_group 0;" ::: "memory")

__device__ __forceinline__ void ldsm4(uint32_t (&r)[4], uint32_t addr) {
    asm volatile("ldmatrix.sync.aligned.m8n8.x4.shared.b16 {%0,%1,%2,%3}, [%4];"
                 : "=r"(r[0]), "=r"(r[1]), "=r"(r[2]), "=r"(r[3]) : "r"(addr));
}
__device__ __forceinline__ void mma_bf16(float (&d)[4], const uint32_t (&a)[4],
                                         uint32_t b0, uint32_t b1) {
    asm volatile("mma.sync.aligned.m16n8k16.row.col.f32.bf16.bf16.f32 "
                 "{%0,%1,%2,%3}, {%4,%5,%6,%7}, {%8,%9}, {%0,%1,%2,%3};"
                 : "+f"(d[0]), "+f"(d[1]), "+f"(d[2]), "+f"(d[3])
                 : "r"(a[0]), "r"(a[1]), "r"(a[2]), "r"(a[3]), "r"(b0), "r"(b1));
}

// smem tile: 128 rows x 4 chunks of 16B. XOR swizzle.
__device__ __forceinline__ uint32_t swz(int row, int chunk) {
    return (uint32_t)(((row << 2) + (chunk ^ ((row >> 1) & 3))) << 4);
}
#define TILE_B  8192
#define STAGE_B (4 * TILE_B)
#define NSTAGE  3
#define DYN_SMEM (NSTAGE * STAGE_B)    // 96 KB

// ---------------- stage loader ----------------
__device__ __forceinline__ void load_stage_dense(
    uint32_t sb, const bf16* __restrict__ Ah, const bf16* __restrict__ Al,
    const bf16* __restrict__ Bh, const bf16* __restrict__ Bl,
    int K, int bm, int n0, int k0, int M, int tid) {
#pragma unroll
    for (int i = 0; i < 2; i++) {
        int cid = tid * 2 + i;
        int row = cid >> 2, ch = cid & 3;
        int gm = bm + row; if (gm >= M) gm = M - 1;
        size_t ga = (size_t)gm * K + k0 + ch * 8;
        uint32_t so = swz(row, ch);
        cpasync16(sb + so, Ah + ga);
        cpasync16(sb + TILE_B + so, Al + ga);
        size_t gb = (size_t)(n0 + row) * K + k0 + ch * 8;
        cpasync16(sb + 2 * TILE_B + so, Bh + gb);
        cpasync16(sb + 3 * TILE_B + so, Bl + gb);
    }
}

// ---------------- warp-tile compute (64x32, bf16x3) ----------------
__device__ __forceinline__ void compute_stage(float (&acc)[4][4][4], uint32_t sb,
                                              int m0w, int n0w, int lane) {
#pragma unroll
    for (int kf = 0; kf < 2; kf++) {
        uint32_t ah[4][4], al[4][4], bh[2][4], bl[2][4];
        const int arow = lane & 15;
        const int ach = kf * 2 + (lane >> 4);
        const int brow = n0w + ((lane >> 4) << 3) + (lane & 7);
        const int bch = kf * 2 + ((lane >> 3) & 1);
#pragma unroll
        for (int mf = 0; mf < 4; mf++)
            ldsm4(ah[mf], sb + swz(m0w + mf * 16 + arow, ach));
#pragma unroll
        for (int p = 0; p < 2; p++)
            ldsm4(bh[p], sb + 2 * TILE_B + swz(brow + p * 16, bch));
#pragma unroll
        for (int mf = 0; mf < 4; mf++)
#pragma unroll
            for (int nf = 0; nf < 4; nf++)
                mma_bf16(acc[mf][nf], ah[mf], bh[nf >> 1][(nf & 1) * 2], bh[nf >> 1][(nf & 1) * 2 + 1]);
#pragma unroll
        for (int p = 0; p < 2; p++)
            ldsm4(bl[p], sb + 3 * TILE_B + swz(brow + p * 16, bch));
#pragma unroll
        for (int mf = 0; mf < 4; mf++)
#pragma unroll
            for (int nf = 0; nf < 4; nf++)
                mma_bf16(acc[mf][nf], ah[mf], bl[nf >> 1][(nf & 1) * 2], bl[nf >> 1][(nf & 1) * 2 + 1]);
#pragma unroll
        for (int mf = 0; mf < 4; mf++)
            ldsm4(al[mf], sb + TILE_B + swz(m0w + mf * 16 + arow, ach));
#pragma unroll
        for (int mf = 0; mf < 4; mf++)
#pragma unroll
            for (int nf = 0; nf < 4; nf++)
                mma_bf16(acc[mf][nf], al[mf], bh[nf >> 1][(nf & 1) * 2], bh[nf >> 1][(nf & 1) * 2 + 1]);
    }
}

// ---------------- GEMM body (shared by layer GEMMs and UV path) ----------------
__device__ __forceinline__ void gemm_body(
    uint32_t sb, const bf16* __restrict__ Ah, const bf16* __restrict__ Al,
    const bf16* __restrict__ Bh, const bf16* __restrict__ Bl,
    float* __restrict__ Cf, __half* __restrict__ Ch,
    int M, int K, int ldcF, int relHalf, int bm, int n0, int tid) {
    const int lane = tid & 31, wid = tid >> 5;
    const int m0w = (wid >> 2) * 64, n0w = (wid & 3) * 32;
    float acc[4][4][4];
#pragma unroll
    for (int a = 0; a < 4; a++)
#pragma unroll
        for (int b = 0; b < 4; b++)
#pragma unroll
            for (int c = 0; c < 4; c++) acc[a][b][c] = 0.f;

    const int niter = K / 32;
    load_stage_dense(sb, Ah, Al, Bh, Bl, K, bm, n0, 0, M, tid);
    CP_COMMIT();
    load_stage_dense(sb + STAGE_B, Ah, Al, Bh, Bl, K, bm, n0, 32, M, tid);
    CP_COMMIT();

    int buf = 0;
    for (int it = 0; it < niter; it++) {
        if (it + 1 < niter) CP_WAIT1(); else CP_WAIT0();
        __syncthreads();
        if (it + 2 < niter) {
            int nb = buf + 2; if (nb >= NSTAGE) nb -= NSTAGE;
            load_stage_dense(sb + nb * STAGE_B, Ah, Al, Bh, Bl, K, bm, n0, (it + 2) * 32, M, tid);
            CP_COMMIT();
        }
        compute_stage(acc, sb + buf * STAGE_B, m0w, n0w, lane);
        if (++buf == NSTAGE) buf = 0;
    }

    const bool halfPath = relHalf && (n0 >= 128);
#pragma unroll
    for (int mf = 0; mf < 4; mf++) {
#pragma unroll
        for (int nf = 0; nf < 4; nf++) {
            int col = n0 + n0w + nf * 8 + (lane & 3) * 2;
            int r0 = bm + m0w + mf * 16 + (lane >> 2);
            int r1 = r0 + 8;
            if (halfPath) {
                int cr = col - 128;
                if (r0 < M)
                    *(__half2*)&Ch[(size_t)r0 * 384 + cr] =
                        __floats2half2_rn(acc[mf][nf][0], acc[mf][nf][1]);
                if (r1 < M)
                    *(__half2*)&Ch[(size_t)r1 * 384 + cr] =
                        __floats2half2_rn(acc[mf][nf][2], acc[mf][nf][3]);
            } else {
                if (r0 < M)
                    *(float2*)&Cf[(size_t)r0 * ldcF + col] = make_float2(acc[mf][nf][0], acc[mf][nf][1]);
                if (r1 < M)
                    *(float2*)&Cf[(size_t)r1 * ldcF + col] = make_float2(acc[mf][nf][2], acc[mf][nf][3]);
            }
        }
    }
}

// ---------------- layer GEMM kernel ----------------
__global__ __launch_bounds__(256)
void gemm_mma(const bf16* __restrict__ Ah, const bf16* __restrict__ Al,
              const bf16* __restrict__ Bh, const bf16* __restrict__ Bl,
              float* __restrict__ Cf, __half* __restrict__ Ch,
              int M, int K, int ldcF, int relHalf) {
    extern __shared__ char dsm[];
    gemm_body(smem_u32(dsm), Ah, Al, Bh, Bl, Cf, Ch, M, K, ldcF, relHalf,
              blockIdx.y * 128, blockIdx.x * 128, threadIdx.x);
}

// ---------------- UV GEMM + node head fused (uniform 96KB dyn smem) ----------------
__global__ __launch_bounds__(256)
void uv_node_kernel(const bf16* __restrict__ Ah, const bf16* __restrict__ Al,
                    const bf16* __restrict__ Bh, const bf16* __restrict__ Bl,
                    float* __restrict__ UV, int gemmBlocks,
                    const bf16* __restrict__ xh, const bf16* __restrict__ xl,
                    const float* __restrict__ Wn1, const float* __restrict__ bn1,
                    const float* __restrict__ Wn2, const float* __restrict__ bn2,
                    float* __restrict__ node_out) {
    extern __shared__ char dsm[];
    const int tid = threadIdx.x;
    if ((int)blockIdx.x < gemmBlocks) {
        int blk = blockIdx.x;
        gemm_body(smem_u32(dsm), Ah, Al, Bh, Bl, UV, (__half*)nullptr,
                  NN, HH, 256, 0, (blk >> 1) * 128, (blk & 1) * 128, tid);
        return;
    }
    // ---- node head path: carve smem out of the 96KB dynamic allocation ----
    float* sW1  = (float*)dsm;                 // 128*64
    float* sb1  = sW1 + 128 * 64;              // 64
    float* sW2  = sb1 + 64;                    // 128
    float* sx   = sW2 + 128;                   // 4*128
    float* sPart = sx + 4 * 128;               // 8*2
    const int team = tid >> 6, t = tid & 63;
    const int wid = tid >> 5, lane = tid & 31;
    for (int i = tid; i < 128 * 64; i += 256) sW1[i] = Wn1[i];
    if (tid < 64) sb1[tid] = bn1[tid];
    if (tid < 128) sW2[tid] = Wn2[tid];
    float b20 = __ldg(&bn2[0]), b21 = __ldg(&bn2[1]);
    __syncthreads();
    const int base = ((int)blockIdx.x - gemmBlocks) * 64;
#pragma unroll 1
    for (int it = 0; it < 16; it++) {
        int node = base + it * 4 + team;
        bool ok = node < NN;
        if (ok) {
            size_t off = (size_t)node * HH;
            sx[team * 128 + t]      = __bfloat162float(xh[off + t])      + __bfloat162float(xl[off + t]);
            sx[team * 128 + t + 64] = __bfloat162float(xh[off + t + 64]) + __bfloat162float(xl[off + t + 64]);
        }
        __syncthreads();
        float p0 = 0.f, p1 = 0.f;
        if (ok) {
            float acc = sb1[t];
#pragma unroll
            for (int k = 0; k < 128; k++) acc += sx[team * 128 + k] * sW1[k * 64 + t];
            float hgt = fmaxf(acc, 0.f);
            p0 = hgt * sW2[t * 2 + 0];
            p1 = hgt * sW2[t * 2 + 1];
        }
#pragma unroll
        for (int o = 16; o; o >>= 1) {
            p0 += __shfl_xor_sync(0xFFFFFFFFu, p0, o);
            p1 += __shfl_xor_sync(0xFFFFFFFFu, p1, o);
        }
        if (lane == 0) { sPart[wid * 2 + 0] = p0; sPart[wid * 2 + 1] = p1; }
        __syncthreads();
        if (ok && t == 0) {
            node_out[(size_t)node * 2 + 0] = sPart[(team * 2) * 2 + 0] + sPart[(team * 2 + 1) * 2 + 0] + b20;
            node_out[(size_t)node * 2 + 1] = sPart[(team * 2) * 2 + 1] + sPart[(team * 2 + 1) * 2 + 1] + b21;
        }
        __syncthreads();
    }
}

// ---------------- prep: pack_all + cnt + split fused via block-range dispatch ----------------
__device__ __forceinline__ void pack_one(float v, bf16* __restrict__ Bh,
                                         bf16* __restrict__ Bl, int idx) {
    bf16 h = __float2bfloat16(v);
    Bh[idx] = h;
    Bl[idx] = __float2bfloat16(v - __bfloat162float(h));
}
__device__ __forceinline__ float layer_w(const float* __restrict__ W_root,
                                         const float* __restrict__ W_rel,
                                         int idx, int K) {
    int n = idx / K, k = idx % K;
    if (n < HH) return W_root[k * HH + n];
    return W_rel[((size_t)((n >> 7) - 1) * K + k) * HH + (n & 127)];
}
#define P1 (512 * INF)
#define P2 (512 * HH)
#define PACK_TOTAL  (P1 + 2 * P2 + 256 * 128)
#define PACK_BLOCKS ((PACK_TOTAL + 255) / 256)
#define SPLIT_N4    (NN * INF / 4)
#define SPLIT_BLOCKS ((SPLIT_N4 + 255) / 256)

__global__ __launch_bounds__(256)
void prep_kernel(const float* __restrict__ Wr1, const float* __restrict__ Wrel1,
                 const float* __restrict__ Wr2, const float* __restrict__ Wrel2,
                 const float* __restrict__ Wr3, const float* __restrict__ Wrel3,
                 const float* __restrict__ We1,
                 bf16* B1h, bf16* B1l, bf16* B2h, bf16* B2l,
                 bf16* B3h, bf16* B3l, bf16* Weh, bf16* Wel,
                 const int* __restrict__ dst, const int* __restrict__ et,
                 int* __restrict__ cnt3, int E, int cntBlocks,
                 const float* __restrict__ x, bf16* __restrict__ xh, bf16* __restrict__ xl) {
    int blk = blockIdx.x;
    if (blk < PACK_BLOCKS) {
        int idx = blk * 256 + threadIdx.x;
        if (idx < P1) {
            pack_one(layer_w(Wr1, Wrel1, idx, INF), B1h, B1l, idx);
        } else if (idx < P1 + P2) {
            int i = idx - P1;
            pack_one(layer_w(Wr2, Wrel2, i, HH), B2h, B2l, i);
        } else if (idx < P1 + 2 * P2) {
            int i = idx - P1 - P2;
            pack_one(layer_w(Wr3, Wrel3, i, HH), B3h, B3l, i);
        } else if (idx < PACK_TOTAL) {
            int i = idx - P1 - 2 * P2;
            int n = i / 128, k = i % 128;
            float v = (n < 128) ? We1[k * 128 + n] : We1[(128 + k) * 128 + (n - 128)];
            pack_one(v, Weh, Wel, i);
        }
        return;
    }
    blk -= PACK_BLOCKS;
    if (blk < cntBlocks) {
        int i = blk * 256 + threadIdx.x;
        if (i < E) atomicAdd(&cnt3[dst[i] * RR + et[i]], 1);
        return;
    }
    blk -= cntBlocks;
    {
        int i = blk * 256 + threadIdx.x;
        if (i >= SPLIT_N4) return;
        float4 v = ((const float4*)x)[i];
        bf16 h0 = __float2bfloat16(v.x), h1 = __float2bfloat16(v.y);
        bf16 h2 = __float2bfloat16(v.z), h3 = __float2bfloat16(v.w);
        ((__nv_bfloat162*)xh)[i * 2]     = __nv_bfloat162(h0, h1);
        ((__nv_bfloat162*)xh)[i * 2 + 1] = __nv_bfloat162(h2, h3);
        ((__nv_bfloat162*)xl)[i * 2]     = __nv_bfloat162(__float2bfloat16(v.x - __bfloat162float(h0)),
                                                          __float2bfloat16(v.y - __bfloat162float(h1)));
        ((__nv_bfloat162*)xl)[i * 2 + 1] = __nv_bfloat162(__float2bfloat16(v.z - __bfloat162float(h2)),
                                                          __float2bfloat16(v.w - __bfloat162float(h3)));
    }
}

// ---------------- scan over cnt3 triplets -> offs ----------------
__global__ void scan_kernel(const int* __restrict__ cnt3, int* __restrict__ offs) {
    __shared__ int warp_sums[32];
    __shared__ int s_carry;
    const int t = threadIdx.x;          // 1024 threads, single block
    const int lane = t & 31, w = t >> 5;
    if (t == 0) { s_carry = 0; offs[0] = 0; }
    __syncthreads();
    for (int base = 0; base < NN; base += 1024) {
        int i = base + t;
        int v = 0;
        if (i < NN)
            v = cnt3[i * RR + 0] + cnt3[i * RR + 1] + cnt3[i * RR + 2];
        int x = v;
#pragma unroll
        for (int o = 1; o < 32; o <<= 1) {
            int y = __shfl_up_sync(0xFFFFFFFFu, x, o);
            if (lane >= o) x += y;
        }
        if (lane == 31) warp_sums[w] = x;
        __syncthreads();
        if (w == 0) {
            int s = warp_sums[lane];
#pragma unroll
            for (int o = 1; o < 32; o <<= 1) {
                int y = __shfl_up_sync(0xFFFFFFFFu, s, o);
                if (lane >= o) s += y;
            }
            warp_sums[lane] = s;
        }
        __syncthreads();
        int incl = x + (w > 0 ? warp_sums[w - 1] : 0) + s_carry;
        if (i < NN) offs[i + 1] = incl;
        __syncthreads();
        if (t == 1023) s_carry = incl;
        __syncthreads();
    }
}

__global__ void fill_kernel(const int* __restrict__ src, const int* __restrict__ dst,
                            const int* __restrict__ et, const int* __restrict__ offs,
                            int* __restrict__ cur, int* __restrict__ epack, int E) {
    int i = blockIdx.x * blockDim.x + threadIdx.x;
    if (i >= E) return;
    int d = dst[i];
    int p = atomicAdd(&cur[d], 1);
    epack[offs[d] + p] = src[i] | (et[i] << 28);
}

// ---------------- fused aggregation: warp/node, fp16 rel gathers ----------------
__device__ __forceinline__ void half8_to_f4(uint2 q, float& x, float& y, float& z, float& w) {
    float2 a = __half22float2(*(__half2*)&q.x);
    float2 b = __half22float2(*(__half2*)&q.y);
    x = a.x; y = a.y; z = b.x; w = b.y;
}

__global__ __launch_bounds__(256)
void agg_combine(const float* __restrict__ hroot, const __half* __restrict__ hrel,
                 const int* __restrict__ offs, const int* __restrict__ epack,
                 const int* __restrict__ cnt3, const float* __restrict__ b,
                 bf16* __restrict__ xh, bf16* __restrict__ xl, int do_relu) {
    int node = (blockIdx.x * blockDim.x + threadIdx.x) >> 5;
    int lane = threadIdx.x & 31;
    if (node >= NN) return;
    const int o0 = offs[node], o1 = offs[node + 1];
    const float w0 = 1.f / (float)max(__ldg(&cnt3[node * RR + 0]), 1);
    const float w1 = 1.f / (float)max(__ldg(&cnt3[node * RR + 1]), 1);
    const float w2 = 1.f / (float)max(__ldg(&cnt3[node * RR + 2]), 1);

    float4 root = *(const float4*)&hroot[(size_t)node * 128 + lane * 4];
    float4 bb = *(const float4*)&b[lane * 4];
    float tx = root.x + bb.x, ty = root.y + bb.y;
    float tz = root.z + bb.z, tw = root.w + bb.w;

    const __half* __restrict__ hb = hrel + lane * 4;
    int e = o0;
    for (; e + 4 <= o1; e += 4) {
        int p0 = __ldg(&epack[e + 0]);
        int p1 = __ldg(&epack[e + 1]);
        int p2 = __ldg(&epack[e + 2]);
        int p3 = __ldg(&epack[e + 3]);
        int r0 = (unsigned)p0 >> 28, r1 = (unsigned)p1 >> 28;
        int r2 = (unsigned)p2 >> 28, r3 = (unsigned)p3 >> 28;
        uint2 q0 = __ldg((const uint2*)(hb + ((size_t)(p0 & 0x0FFFFFFF) * 384 + (r0 << 7))));
        uint2 q1 = __ldg((const uint2*)(hb + ((size_t)(p1 & 0x0FFFFFFF) * 384 + (r1 << 7))));
        uint2 q2 = __ldg((const uint2*)(hb + ((size_t)(p2 & 0x0FFFFFFF) * 384 + (r2 << 7))));
        uint2 q3 = __ldg((const uint2*)(hb + ((size_t)(p3 & 0x0FFFFFFF) * 384 + (r3 << 7))));
        float ws0 = (r0 == 0) ? w0 : ((r0 == 1) ? w1 : w2);
        float ws1 = (r1 == 0) ? w0 : ((r1 == 1) ? w1 : w2);
        float ws2 = (r2 == 0) ? w0 : ((r2 == 1) ? w1 : w2);
        float ws3 = (r3 == 0) ? w0 : ((r3 == 1) ? w1 : w2);
        float vx, vy, vz, vw;
        half8_to_f4(q0, vx, vy, vz, vw);
        tx += vx * ws0; ty += vy * ws0; tz += vz * ws0; tw += vw * ws0;
        half8_to_f4(q1, vx, vy, vz, vw);
        tx += vx * ws1; ty += vy * ws1; tz += vz * ws1; tw += vw * ws1;
        half8_to_f4(q2, vx, vy, vz, vw);
        tx += vx * ws2; ty += vy * ws2; tz += vz * ws2; tw += vw * ws2;
        half8_to_f4(q3, vx, vy, vz, vw);
        tx += vx * ws3; ty += vy * ws3; tz += vz * ws3; tw += vw * ws3;
    }
    if (e + 2 <= o1) {
        int p0 = __ldg(&epack[e + 0]);
        int p1 = __ldg(&epack[e + 1]);
        int r0 = (unsigned)p0 >> 28, r1 = (unsigned)p1 >> 28;
        uint2 q0 = __ldg((const uint2*)(hb + ((size_t)(p0 & 0x0FFFFFFF) * 384 + (r0 << 7))));
        uint2 q1 = __ldg((const uint2*)(hb + ((size_t)(p1 & 0x0FFFFFFF) * 384 + (r1 << 7))));
        float ws0 = (r0 == 0) ? w0 : ((r0 == 1) ? w1 : w2);
        float ws1 = (r1 == 0) ? w0 : ((r1 == 1) ? w1 : w2);
        float vx, vy, vz, vw;
        half8_to_f4(q0, vx, vy, vz, vw);
        tx += vx * ws0; ty += vy * ws0; tz += vz * ws0; tw += vw * ws0;
        half8_to_f4(q1, vx, vy, vz, vw);
        tx += vx * ws1; ty += vy * ws1; tz += vz * ws1; tw += vw * ws1;
        e += 2;
    }
    if (e < o1) {
        int p0 = __ldg(&epack[e]);
        int r0 = (unsigned)p0 >> 28;
        uint2 q0 = __ldg((const uint2*)(hb + ((size_t)(p0 & 0x0FFFFFFF) * 384 + (r0 << 7))));
        float ws0 = (r0 == 0) ? w0 : ((r0 == 1) ? w1 : w2);
        float vx, vy, vz, vw;
        half8_to_f4(q0, vx, vy, vz, vw);
        tx += vx * ws0; ty += vy * ws0; tz += vz * ws0; tw += vw * ws0;
    }

    if (do_relu) {
        tx = fmaxf(tx, 0.f); ty = fmaxf(ty, 0.f);
        tz = fmaxf(tz, 0.f); tw = fmaxf(tw, 0.f);
    }
    size_t idx = (size_t)node * HH + lane * 4;
    bf16 h0 = __float2bfloat16(tx), h1 = __float2bfloat16(ty);
    bf16 h2 = __float2bfloat16(tz), h3 = __float2bfloat16(tw);
    __nv_bfloat162 hh0(h0, h1), hh1(h2, h3);
    *(uint2*)&xh[idx] = make_uint2(*(uint32_t*)&hh0, *(uint32_t*)&hh1);
    __nv_bfloat162 ll0(__float2bfloat16(tx - __bfloat162float(h0)),
                       __float2bfloat16(ty - __bfloat162float(h1)));
    __nv_bfloat162 ll1(__float2bfloat16(tz - __bfloat162float(h2)),
                       __float2bfloat16(tw - __bfloat162float(h3)));
    *(uint2*)&xl[idx] = make_uint2(*(uint32_t*)&ll0, *(uint32_t*)&ll1);
}

// ---------------- edge apply: warp handles TWO edges (MLP=4) ----------------
__global__ __launch_bounds__(256)
void edge_apply(const float* __restrict__ UV,
                const int* __restrict__ src, const int* __restrict__ dst,
                const float* __restrict__ be1, const float* __restrict__ We2,
                const float* __restrict__ be2, float* __restrict__ out, int E) {
    __shared__ float sBe1[128];
    __shared__ float sW2[384];
    const int tid = threadIdx.x, lane = tid & 31;
    if (tid < 128) sBe1[tid] = be1[tid];
    for (int v = tid; v < 384; v += 256) sW2[v] = We2[v];
    __syncthreads();
    int gw = (blockIdx.x * 256 + tid) >> 5;
    int e0 = gw * 2;
    if (e0 >= E) return;
    int e1 = e0 + 1;
    bool has1 = e1 < E;
    int s0 = src[e0], d0 = dst[e0];
    int s1 = has1 ? src[e1] : s0;
    int d1 = has1 ? dst[e1] : d0;
    const int c = lane * 4;
    float4 u0 = __ldg((const float4*)(UV + (size_t)s0 * 256 + c));
    float4 v0 = __ldg((const float4*)(UV + (size_t)d0 * 256 + 128 + c));
    float4 u1 = __ldg((const float4*)(UV + (size_t)s1 * 256 + c));
    float4 v1 = __ldg((const float4*)(UV + (size_t)d1 * 256 + 128 + c));
    float be0 = sBe1[c + 0], be1_ = sBe1[c + 1], be2_ = sBe1[c + 2], be3 = sBe1[c + 3];
    float wa0 = sW2[(c + 0) * 3], wb0 = sW2[(c + 0) * 3 + 1], wc0 = sW2[(c + 0) * 3 + 2];
    float wa1 = sW2[(c + 1) * 3], wb1 = sW2[(c + 1) * 3 + 1], wc1 = sW2[(c + 1) * 3 + 2];
    float wa2 = sW2[(c + 2) * 3], wb2 = sW2[(c + 2) * 3 + 1], wc2 = sW2[(c + 2) * 3 + 2];
    float wa3 = sW2[(c + 3) * 3], wb3 = sW2[(c + 3) * 3 + 1], wc3 = sW2[(c + 3) * 3 + 2];

    float h;
    float a00 = 0.f, a01 = 0.f, a02 = 0.f;
    h = fmaxf(u0.x + v0.x + be0, 0.f); a00 += h * wa0; a01 += h * wb0; a02 += h * wc0;
    h = fmaxf(u0.y + v0.y + be1_, 0.f); a00 += h * wa1; a01 += h * wb1; a02 += h * wc1;
    h = fmaxf(u0.z + v0.z + be2_, 0.f); a00 += h * wa2; a01 += h * wb2; a02 += h * wc2;
    h = fmaxf(u0.w + v0.w + be3, 0.f); a00 += h * wa3; a01 += h * wb3; a02 += h * wc3;
    float a10 = 0.f, a11 = 0.f, a12 = 0.f;
    h = fmaxf(u1.x + v1.x + be0, 0.f); a10 += h * wa0; a11 += h * wb0; a12 += h * wc0;
    h = fmaxf(u1.y + v1.y + be1_, 0.f); a10 += h * wa1; a11 += h * wb1; a12 += h * wc1;
    h = fmaxf(u1.z + v1.z + be2_, 0.f); a10 += h * wa2; a11 += h * wb2; a12 += h * wc2;
    h = fmaxf(u1.w + v1.w + be3, 0.f); a10 += h * wa3; a11 += h * wb3; a12 += h * wc3;
#pragma unroll
    for (int o = 16; o; o >>= 1) {
        a00 += __shfl_xor_sync(0xFFFFFFFFu, a00, o);
        a01 += __shfl_xor_sync(0xFFFFFFFFu, a01, o);
        a02 += __shfl_xor_sync(0xFFFFFFFFu, a02, o);
        a10 += __shfl_xor_sync(0xFFFFFFFFu, a10, o);
        a11 += __shfl_xor_sync(0xFFFFFFFFu, a11, o);
        a12 += __shfl_xor_sync(0xFFFFFFFFu, a12, o);
    }
    if (lane == 0) {
        float g0 = __ldg(&be2[0]), g1 = __ldg(&be2[1]), g2 = __ldg(&be2[2]);
        out[(size_t)e0 * 3 + 0] = a00 + g0;
        out[(size_t)e0 * 3 + 1] = a01 + g1;
        out[(size_t)e0 * 3 + 2] = a02 + g2;
        if (has1) {
            out[(size_t)e1 * 3 + 0] = a10 + g0;
            out[(size_t)e1 * 3 + 1] = a11 + g1;
            out[(size_t)e1 * 3 + 2] = a12 + g2;
        }
    }
}

// ---------------- launch ----------------
extern "C" void kernel_launch(void* const* d_in, const int* in_sizes, int n_in,
                              void* d_out, int out_size) {
    const float* x       = (const float*)d_in[0];
    const int*   ei      = (const int*)d_in[1];
    const int*   et      = (const int*)d_in[2];
    const float* W_rel1  = (const float*)d_in[3];
    const float* W_root1 = (const float*)d_in[4];
    const float* b1      = (const float*)d_in[5];
    const float* W_rel2  = (const float*)d_in[6];
    const float* W_root2 = (const float*)d_in[7];
    const float* b2      = (const float*)d_in[8];
    const float* W_rel3  = (const float*)d_in[9];
    const float* W_root3 = (const float*)d_in[10];
    const float* b3      = (const float*)d_in[11];
    const float* We1     = (const float*)d_in[12];
    const float* be1     = (const float*)d_in[13];
    const float* We2     = (const float*)d_in[14];
    const float* be2     = (const float*)d_in[15];
    const float* Wn1     = (const float*)d_in[16];
    const float* bn1     = (const float*)d_in[17];
    const float* Wn2     = (const float*)d_in[18];
    const float* bn2     = (const float*)d_in[19];

    const int E = in_sizes[2];
    const int* src = ei;
    const int* dst = ei + E;

    bf16 *B1h, *B1l, *B2h, *B2l, *B3h, *B3l, *Weh, *Wel, *xh, *xl;
    float *hroot, *UV;
    __half *hrel;
    int *offs, *cur, *cnt3, *epack;
    cudaGetSymbolAddress((void**)&B1h, g_B1h);
    cudaGetSymbolAddress((void**)&B1l, g_B1l);
    cudaGetSymbolAddress((void**)&B2h, g_B2h);
    cudaGetSymbolAddress((void**)&B2l, g_B2l);
    cudaGetSymbolAddress((void**)&B3h, g_B3h);
    cudaGetSymbolAddress((void**)&B3l, g_B3l);
    cudaGetSymbolAddress((void**)&Weh, g_Weh);
    cudaGetSymbolAddress((void**)&Wel, g_Wel);
    cudaGetSymbolAddress((void**)&xh, g_xh);
    cudaGetSymbolAddress((void**)&xl, g_xl);
    cudaGetSymbolAddress((void**)&hroot, g_hroot);
    cudaGetSymbolAddress((void**)&hrel, g_hrel);
    cudaGetSymbolAddress((void**)&UV, g_UV);
    cudaGetSymbolAddress((void**)&offs, g_offs);
    cudaGetSymbolAddress((void**)&cur, g_cur);
    cudaGetSymbolAddress((void**)&cnt3, g_cnt3);
    cudaGetSymbolAddress((void**)&epack, g_epack);

    cudaFuncSetAttribute(gemm_mma, cudaFuncAttributeMaxDynamicSharedMemorySize, DYN_SMEM);
    cudaFuncSetAttribute(uv_node_kernel, cudaFuncAttributeMaxDynamicSharedMemorySize, DYN_SMEM);

    float* out = (float*)d_out;
    float* edge_out = out;
    float* node_out = out + (size_t)E * 3;

    const int aggBlocks = (NN * 32 + 255) / 256;
    const int cntBlocks = (E + 255) / 256;
    const int edgeWarps = (E + 1) / 2;
    const int edgeBlocks = (edgeWarps * 32 + 255) / 256;
    const int uvGemmBlocks = 2 * ((NN + 127) / 128);
    const int nodeBlocks = (NN + 63) / 64;
    dim3 gemmGrid(4, (NN + 127) / 128);

    // ---- upfront (fused): weight packs + edge counts + input split ----
    cudaMemsetAsync(cur, 0, NN * sizeof(int));
    cudaMemsetAsync(cnt3, 0, NN * RR * sizeof(int));
    prep_kernel<<<PACK_BLOCKS + cntBlocks + SPLIT_BLOCKS, 256>>>(
        W_root1, W_rel1, W_root2, W_rel2, W_root3, W_rel3, We1,
        B1h, B1l, B2h, B2l, B3h, B3l, Weh, Wel,
        dst, et, cnt3, E, cntBlocks, x, xh, xl);
    scan_kernel<<<1, 1024>>>(cnt3, offs);
    fill_kernel<<<cntBlocks, 256>>>(src, dst, et, offs, cur, epack, E);

    // ---- layer 1 ----
    gemm_mma<<<gemmGrid, 256, DYN_SMEM>>>(xh, xl, B1h, B1l, hroot, hrel, NN, INF, 128, 1);
    agg_combine<<<aggBlocks, 256>>>(hroot, hrel, offs, epack, cnt3, b1, xh, xl, 1);

    // ---- layer 2 ----
    gemm_mma<<<gemmGrid, 256, DYN_SMEM>>>(xh, xl, B2h, B2l, hroot, hrel, NN, HH, 128, 1);
    agg_combine<<<aggBlocks, 256>>>(hroot, hrel, offs, epack, cnt3, b2, xh, xl, 1);

    // ---- layer 3 (no relu) ----
    gemm_mma<<<gemmGrid, 256, DYN_SMEM>>>(xh, xl, B3h, B3l, hroot, hrel, NN, HH, 128, 1);
    agg_combine<<<aggBlocks, 256>>>(hroot, hrel, offs, epack, cnt3, b3, xh, xl, 0);

    // ---- edge head UV GEMM + node head (fused launch; uniform 96KB smem) ----
    uv_node_kernel<<<uvGemmBlocks + nodeBlocks, 256, DYN_SMEM>>>(
        xh, xl, Weh, Wel, UV, uvGemmBlocks,
        xh, xl, Wn1, bn1, Wn2, bn2, node_out);

    // ---- edge apply (2 edges/warp) ----
    edge_apply<<<edgeBlocks, 256>>>(UV, src, dst, be1, We2, be2, edge_out, E);
}